// round 1
// baseline (speedup 1.0000x reference)
#include <cuda_runtime.h>
#include <math.h>

#define B_SZ   2048
#define HW     64
#define C1     15
#define C2     30
#define P1     29          // pooled1 spatial (58/2)
#define P2     11          // pooled2 spatial (23/2 floor)
#define K1ELEM (C1*49)     // 735
#define K2ELEM (C2*C1*49)  // 22050
#define FC1IN  (C2*P2*P2)  // 3630
#define FC1OUT 200
#define FC2OUT 2

// ---------------- scratch (static device allocations) ----------------
__device__ float g_pcen [B_SZ * HW * HW];          // [B,64,64]
__device__ float g_pool1[B_SZ * C1 * P1 * P1];     // [B,15,29,29]
__device__ float g_pool2[B_SZ * C2 * P2 * P2];     // [B,30,11,11]
__device__ float g_fc1  [B_SZ * FC1OUT];           // [B,200]

// ---------------- PCEN: EMA over W per (b,h) row ----------------
__global__ void pcen_kernel(const float* __restrict__ x,
                            const float* __restrict__ log_s,
                            const float* __restrict__ log_alpha,
                            const float* __restrict__ log_delta,
                            const float* __restrict__ log_r,
                            float* __restrict__ out) {
    int idx = blockIdx.x * blockDim.x + threadIdx.x;   // b*64 + h
    if (idx >= B_SZ * HW) return;
    const float s     = expf(log_s[0]);
    const float alpha = expf(log_alpha[0]);
    const float delta = expf(log_delta[0]);
    const float r     = expf(log_r[0]);
    const float dr    = powf(delta, r);
    const float* row  = x   + (size_t)idx * HW;
    float*       orow = out + (size_t)idx * HW;
    float m = 0.f;
    #pragma unroll 8
    for (int w = 0; w < HW; ++w) {
        float v = __ldg(row + w);
        m = (1.f - s) * m + s * v;                      // m0 = s*x0 (m starts 0)
        float denom = powf(m + 1e-6f, alpha);
        orow[w] = powf(v / denom + delta, r) - dr;
    }
}

// ---------------- conv1 (1->15, 7x7) + BN + ReLU + maxpool2 ----------------
// one block per image; full 64x64 input tile in smem
__global__ void conv1_kernel(const float* __restrict__ pcen,
                             const float* __restrict__ w,
                             const float* __restrict__ cb,
                             const float* __restrict__ g,
                             const float* __restrict__ beta,
                             const float* __restrict__ mean,
                             const float* __restrict__ var,
                             float* __restrict__ out) {
    __shared__ float sIn[HW * HW];          // 16 KB
    __shared__ float sW[K1ELEM];            // 735
    __shared__ float sScale[C1], sBias[C1];

    int b = blockIdx.x;
    const float* in = pcen + (size_t)b * HW * HW;
    for (int i = threadIdx.x; i < HW * HW; i += blockDim.x) sIn[i] = in[i];
    for (int i = threadIdx.x; i < K1ELEM;  i += blockDim.x) sW[i]  = w[i];
    if (threadIdx.x < C1) {
        int c = threadIdx.x;
        float inv = g[c] * rsqrtf(var[c] + 1e-5f);
        sScale[c] = inv;
        sBias[c]  = cb[c] * inv + beta[c] - mean[c] * inv;
    }
    __syncthreads();

    float* ob = out + (size_t)b * C1 * P1 * P1;
    for (int o = threadIdx.x; o < C1 * P1 * P1; o += blockDim.x) {
        int c   = o / (P1 * P1);
        int rem = o % (P1 * P1);
        int oy  = rem / P1, ox = rem % P1;
        const float* wc = sW + c * 49;
        float scale = sScale[c], bias = sBias[c];
        float mx = -1e30f;
        #pragma unroll
        for (int dy = 0; dy < 2; ++dy) {
            #pragma unroll
            for (int dx = 0; dx < 2; ++dx) {
                int py = 2 * oy + dy, px = 2 * ox + dx;
                float acc = 0.f;
                #pragma unroll
                for (int ky = 0; ky < 7; ++ky) {
                    #pragma unroll
                    for (int kx = 0; kx < 7; ++kx)
                        acc = fmaf(sIn[(py + ky) * HW + px + kx], wc[ky * 7 + kx], acc);
                }
                mx = fmaxf(mx, acc * scale + bias);     // BN before max (scale sign unknown)
            }
        }
        ob[o] = fmaxf(mx, 0.f);
    }
}

// ---------------- conv2 (15->30, 7x7) + BN + ReLU + maxpool2 ----------------
// one block per (image, out-channel); stream ic-slabs through smem;
// each thread owns one pooled cell = 4 accumulators
__global__ void conv2_kernel(const float* __restrict__ pool1,
                             const float* __restrict__ w,
                             const float* __restrict__ cb,
                             const float* __restrict__ g,
                             const float* __restrict__ beta,
                             const float* __restrict__ mean,
                             const float* __restrict__ var,
                             float* __restrict__ out) {
    __shared__ float sIn[P1 * P1];      // 841
    __shared__ float sW[C1 * 49];       // 735

    int b = blockIdx.x / C2;
    int c = blockIdx.x % C2;
    const float* in = pool1 + (size_t)b * C1 * P1 * P1;
    const float* wc = w + (size_t)c * C1 * 49;
    for (int i = threadIdx.x; i < C1 * 49; i += blockDim.x) sW[i] = wc[i];

    float inv   = g[c] * rsqrtf(var[c] + 1e-5f);
    float scale = inv;
    float bias  = cb[c] * inv + beta[c] - mean[c] * inv;

    int oy = threadIdx.x / P2, ox = threadIdx.x % P2;
    bool active = threadIdx.x < P2 * P2;

    float a00 = 0.f, a01 = 0.f, a10 = 0.f, a11 = 0.f;

    for (int ic = 0; ic < C1; ++ic) {
        __syncthreads();
        for (int i = threadIdx.x; i < P1 * P1; i += blockDim.x)
            sIn[i] = in[ic * P1 * P1 + i];
        __syncthreads();
        if (active) {
            const float* wi = sW + ic * 49;
            #pragma unroll
            for (int ky = 0; ky < 7; ++ky) {
                int base = (2 * oy + ky) * P1 + 2 * ox;
                #pragma unroll
                for (int kx = 0; kx < 7; ++kx) {
                    float wv = wi[ky * 7 + kx];
                    a00 = fmaf(sIn[base + kx],           wv, a00);
                    a01 = fmaf(sIn[base + kx + 1],       wv, a01);
                    a10 = fmaf(sIn[base + kx + P1],      wv, a10);
                    a11 = fmaf(sIn[base + kx + P1 + 1],  wv, a11);
                }
            }
        }
    }

    if (active) {
        float mx = fmaxf(fmaxf(a00 * scale + bias, a01 * scale + bias),
                         fmaxf(a10 * scale + bias, a11 * scale + bias));
        out[(size_t)b * C2 * P2 * P2 + c * P2 * P2 + threadIdx.x] = fmaxf(mx, 0.f);
    }
}

// ---------------- FC1: [2048,3630] x [200,3630]^T + bias, ReLU ----------------
__global__ void fc1_kernel(const float* __restrict__ A,
                           const float* __restrict__ W,
                           const float* __restrict__ bias,
                           float* __restrict__ out) {
    __shared__ float sA[16][17];
    __shared__ float sW[16][17];
    int tx = threadIdx.x, ty = threadIdx.y;
    int n = blockIdx.x * 16 + tx;          // output feature
    int b = blockIdx.y * 16 + ty;          // batch row
    float acc = 0.f;
    for (int k0 = 0; k0 < FC1IN; k0 += 16) {
        int ka = k0 + tx;
        sA[ty][tx] = (ka < FC1IN) ? A[(size_t)b * FC1IN + ka] : 0.f;
        int nw = blockIdx.x * 16 + ty;
        sW[ty][tx] = (nw < FC1OUT && ka < FC1IN) ? W[(size_t)nw * FC1IN + ka] : 0.f;
        __syncthreads();
        #pragma unroll
        for (int kk = 0; kk < 16; ++kk)
            acc = fmaf(sA[ty][kk], sW[tx][kk], acc);
        __syncthreads();
    }
    if (n < FC1OUT)
        out[(size_t)b * FC1OUT + n] = fmaxf(acc + bias[n], 0.f);
}

// ---------------- FC2 + sigmoid ----------------
__global__ void fc2_kernel(const float* __restrict__ A,
                           const float* __restrict__ W,
                           const float* __restrict__ bias,
                           float* __restrict__ out) {
    int idx = blockIdx.x * blockDim.x + threadIdx.x;  // b*2 + n
    if (idx >= B_SZ * FC2OUT) return;
    int b = idx >> 1, n = idx & 1;
    const float* a  = A + (size_t)b * FC1OUT;
    const float* wr = W + (size_t)n * FC1OUT;
    float acc = bias[n];
    #pragma unroll 8
    for (int k = 0; k < FC1OUT; ++k)
        acc = fmaf(a[k], wr[k], acc);
    out[idx] = 1.f / (1.f + expf(-acc));
}

// ---------------- launch ----------------
extern "C" void kernel_launch(void* const* d_in, const int* in_sizes, int n_in,
                              void* d_out, int out_size) {
    const float* x        = (const float*)d_in[0];
    const float* log_s    = (const float*)d_in[1];
    const float* log_a    = (const float*)d_in[2];
    const float* log_d    = (const float*)d_in[3];
    const float* log_r    = (const float*)d_in[4];
    const float* c1w      = (const float*)d_in[5];
    const float* c1b      = (const float*)d_in[6];
    const float* bn1g     = (const float*)d_in[7];
    const float* bn1b     = (const float*)d_in[8];
    const float* bn1m     = (const float*)d_in[9];
    const float* bn1v     = (const float*)d_in[10];
    const float* c2w      = (const float*)d_in[11];
    const float* c2b      = (const float*)d_in[12];
    const float* bn2g     = (const float*)d_in[13];
    const float* bn2b     = (const float*)d_in[14];
    const float* bn2m     = (const float*)d_in[15];
    const float* bn2v     = (const float*)d_in[16];
    const float* fc1w     = (const float*)d_in[17];
    const float* fc1b     = (const float*)d_in[18];
    const float* fc2w     = (const float*)d_in[19];
    const float* fc2b     = (const float*)d_in[20];
    float* out = (float*)d_out;

    float* pcen;  cudaGetSymbolAddress((void**)&pcen,  g_pcen);
    float* pool1; cudaGetSymbolAddress((void**)&pool1, g_pool1);
    float* pool2; cudaGetSymbolAddress((void**)&pool2, g_pool2);
    float* fc1o;  cudaGetSymbolAddress((void**)&fc1o,  g_fc1);

    pcen_kernel<<<(B_SZ * HW + 255) / 256, 256>>>(x, log_s, log_a, log_d, log_r, pcen);

    conv1_kernel<<<B_SZ, 256>>>(pcen, c1w, c1b, bn1g, bn1b, bn1m, bn1v, pool1);

    conv2_kernel<<<B_SZ * C2, 128>>>(pool1, c2w, c2b, bn2g, bn2b, bn2m, bn2v, pool2);

    dim3 fc1grid((FC1OUT + 15) / 16, B_SZ / 16);
    fc1_kernel<<<fc1grid, dim3(16, 16)>>>(pool2, fc1w, fc1b, fc1o);

    fc2_kernel<<<(B_SZ * FC2OUT + 255) / 256, 256>>>(fc1o, fc2w, fc2b, out);
}

// round 2
// speedup vs baseline: 1.3753x; 1.3753x over previous
#include <cuda_runtime.h>
#include <math.h>

#define B_SZ   2048
#define HW     64
#define C1     15
#define C2     30
#define P1     29          // pooled1 spatial (58/2)
#define P2     11          // pooled2 spatial (23/2 floor)
#define FC1IN  (C2*P2*P2)  // 3630
#define FC1OUT 200
#define FC2OUT 2

typedef unsigned long long u64;

// ---------------- f32x2 packed helpers (Blackwell FFMA2) ----------------
__device__ __forceinline__ u64 ffma2(u64 a, u64 b, u64 c) {
    u64 d;
    asm("fma.rn.f32x2 %0, %1, %2, %3;" : "=l"(d) : "l"(a), "l"(b), "l"(c));
    return d;
}
__device__ __forceinline__ u64 pack2(float lo, float hi) {
    u64 d;
    asm("mov.b64 %0, {%1, %2};" : "=l"(d) : "f"(lo), "f"(hi));
    return d;
}
__device__ __forceinline__ u64 dup2(float v) { return pack2(v, v); }
__device__ __forceinline__ float2 unpack2(u64 v) {
    float2 r;
    asm("mov.b64 {%0, %1}, %2;" : "=f"(r.x), "=f"(r.y) : "l"(v));
    return r;
}

// ---------------- scratch (static device allocations) ----------------
__device__ float g_pcen [B_SZ * HW * HW];          // [B,64,64]
__device__ float g_pool1[B_SZ * C1 * P1 * P1];     // [B,15,29,29]
__device__ float g_pool2[B_SZ * C2 * P2 * P2];     // [B,30,11,11]
__device__ float g_fc1  [B_SZ * FC1OUT];           // [B,200]

// ---------------- PCEN: EMA over W per (b,h) row ----------------
__global__ void pcen_kernel(const float* __restrict__ x,
                            const float* __restrict__ log_s,
                            const float* __restrict__ log_alpha,
                            const float* __restrict__ log_delta,
                            const float* __restrict__ log_r,
                            float* __restrict__ out) {
    int idx = blockIdx.x * blockDim.x + threadIdx.x;   // b*64 + h
    if (idx >= B_SZ * HW) return;
    const float s     = expf(log_s[0]);
    const float alpha = expf(log_alpha[0]);
    const float delta = expf(log_delta[0]);
    const float r     = expf(log_r[0]);
    const float dr    = powf(delta, r);
    const float* row  = x   + (size_t)idx * HW;
    float*       orow = out + (size_t)idx * HW;
    float m = 0.f;
    #pragma unroll 8
    for (int w = 0; w < HW; ++w) {
        float v = __ldg(row + w);
        m = (1.f - s) * m + s * v;                      // m0 = s*x0 (m starts 0)
        float denom = powf(m + 1e-6f, alpha);
        orow[w] = powf(v / denom + delta, r) - dr;
    }
}

// ---------------- conv1 (1->15 padded to 16, 7x7) + BN + ReLU + maxpool2 ----
// grid (B, 2): blockIdx.y selects 4 oc-pairs (8 channels). Weights stored
// oc-pair interleaved (float2) so one broadcast LDS.64 feeds an FFMA2.
__global__ void __launch_bounds__(256, 2)
conv1_kernel(const float* __restrict__ pcen,
             const float* __restrict__ w,
             const float* __restrict__ cb,
             const float* __restrict__ g,
             const float* __restrict__ beta,
             const float* __restrict__ mean,
             const float* __restrict__ var,
             float* __restrict__ out) {
    __shared__ __align__(16) float  sIn[HW * HW];   // 16 KB
    __shared__ __align__(16) float2 sW2[4 * 49];    // 4 pairs x 49 taps
    __shared__ float sScale[8], sBias[8];

    const int b     = blockIdx.x;
    const int group = blockIdx.y;      // pairs group*4 .. group*4+3
    const int tid   = threadIdx.x;

    const float* in = pcen + (size_t)b * HW * HW;
    for (int i = tid; i < HW * HW; i += 256) sIn[i] = in[i];
    for (int j = tid; j < 4 * 49; j += 256) {
        int p  = j / 49, t = j % 49;
        int oa = (group * 4 + p) * 2;
        int ob = oa + 1;
        float wa = w[oa * 49 + t];
        float wb = (ob < C1) ? w[ob * 49 + t] : 0.f;
        sW2[j] = make_float2(wa, wb);
    }
    if (tid < 8) {
        int oc = group * 8 + tid;
        if (oc < C1) {
            float inv = g[oc] * rsqrtf(var[oc] + 1e-5f);
            sScale[tid] = inv;
            sBias[tid]  = cb[oc] * inv + beta[oc] - mean[oc] * inv;
        } else { sScale[tid] = 0.f; sBias[tid] = 0.f; }
    }
    __syncthreads();

    float* ob_base = out + (size_t)b * C1 * P1 * P1;

    for (int cell = tid; cell < P1 * P1; cell += 256) {
        int oy = cell / P1, ox = cell % P1;
        u64 acc[4][4];
        #pragma unroll
        for (int p = 0; p < 4; ++p)
            #pragma unroll
            for (int q = 0; q < 4; ++q) acc[p][q] = 0ULL;

        for (int ky = 0; ky < 7; ++ky) {
            const float* rp0 = &sIn[(2 * oy + ky) * HW + 2 * ox];
            const float* rp1 = rp0 + HW;
            float2 A0 = *(const float2*)(rp0 + 0);
            float2 A1 = *(const float2*)(rp0 + 2);
            float2 A2 = *(const float2*)(rp0 + 4);
            float2 A3 = *(const float2*)(rp0 + 6);
            float2 B0 = *(const float2*)(rp1 + 0);
            float2 B1 = *(const float2*)(rp1 + 2);
            float2 B2 = *(const float2*)(rp1 + 4);
            float2 B3 = *(const float2*)(rp1 + 6);
            u64 d0[8], d1[8];
            d0[0]=dup2(A0.x); d0[1]=dup2(A0.y); d0[2]=dup2(A1.x); d0[3]=dup2(A1.y);
            d0[4]=dup2(A2.x); d0[5]=dup2(A2.y); d0[6]=dup2(A3.x); d0[7]=dup2(A3.y);
            d1[0]=dup2(B0.x); d1[1]=dup2(B0.y); d1[2]=dup2(B1.x); d1[3]=dup2(B1.y);
            d1[4]=dup2(B2.x); d1[5]=dup2(B2.y); d1[6]=dup2(B3.x); d1[7]=dup2(B3.y);
            #pragma unroll
            for (int p = 0; p < 4; ++p) {
                const float2* wr = &sW2[p * 49 + ky * 7];
                #pragma unroll
                for (int kx = 0; kx < 7; ++kx) {
                    u64 wv = *(const u64*)(wr + kx);
                    acc[p][0] = ffma2(d0[kx],     wv, acc[p][0]);
                    acc[p][1] = ffma2(d0[kx + 1], wv, acc[p][1]);
                    acc[p][2] = ffma2(d1[kx],     wv, acc[p][2]);
                    acc[p][3] = ffma2(d1[kx + 1], wv, acc[p][3]);
                }
            }
        }

        #pragma unroll
        for (int p = 0; p < 4; ++p) {
            float2 v0 = unpack2(acc[p][0]);
            float2 v1 = unpack2(acc[p][1]);
            float2 v2 = unpack2(acc[p][2]);
            float2 v3 = unpack2(acc[p][3]);
            int la = 2 * p, lb = 2 * p + 1;
            int oa = group * 8 + la, obc = group * 8 + lb;
            float sa = sScale[la], ba = sBias[la];
            float mA = fmaxf(fmaxf(v0.x * sa + ba, v1.x * sa + ba),
                             fmaxf(v2.x * sa + ba, v3.x * sa + ba));
            ob_base[oa * (P1 * P1) + cell] = fmaxf(mA, 0.f);
            if (obc < C1) {
                float sb = sScale[lb], bb = sBias[lb];
                float mB = fmaxf(fmaxf(v0.y * sb + bb, v1.y * sb + bb),
                                 fmaxf(v2.y * sb + bb, v3.y * sb + bb));
                ob_base[obc * (P1 * P1) + cell] = fmaxf(mB, 0.f);
            }
        }
    }
}

// ---------------- conv2 (15->30, 7x7) + BN + ReLU + maxpool2 ----------------
// grid (B, 5): each block does 6 output channels (3 FFMA2 pairs) for one image.
// Input streamed in 5-ic slabs (rows padded to 30 for aligned float2 loads).
__global__ void __launch_bounds__(128, 4)
conv2_kernel(const float* __restrict__ pool1,
             const float* __restrict__ w,
             const float* __restrict__ cb,
             const float* __restrict__ g,
             const float* __restrict__ beta,
             const float* __restrict__ mean,
             const float* __restrict__ var,
             float* __restrict__ out) {
    __shared__ __align__(16) float  sIn[5 * P1 * 30];   // 5 ic x 29 x 30 pad
    __shared__ __align__(16) float2 sW2[3 * C1 * 49];   // 3 pairs x 735
    __shared__ float sScale[6], sBias[6];

    const int b   = blockIdx.x;
    const int oc0 = blockIdx.y * 6;
    const int tid = threadIdx.x;

    for (int j = tid; j < 3 * C1 * 49; j += 128) {
        int p = j / (C1 * 49), t = j % (C1 * 49);
        sW2[j] = make_float2(w[(oc0 + 2 * p)     * (C1 * 49) + t],
                             w[(oc0 + 2 * p + 1) * (C1 * 49) + t]);
    }
    if (tid < 6) {
        int oc = oc0 + tid;
        float inv = g[oc] * rsqrtf(var[oc] + 1e-5f);
        sScale[tid] = inv;
        sBias[tid]  = cb[oc] * inv + beta[oc] - mean[oc] * inv;
    }

    const float* in = pool1 + (size_t)b * C1 * P1 * P1;
    const int oy = tid / P2, ox = tid % P2;
    const bool active = tid < P2 * P2;

    u64 acc[3][4];
    #pragma unroll
    for (int p = 0; p < 3; ++p)
        #pragma unroll
        for (int q = 0; q < 4; ++q) acc[p][q] = 0ULL;

    for (int s = 0; s < 3; ++s) {
        __syncthreads();
        for (int j = tid; j < 5 * P1 * P1; j += 128) {
            int icl = j / (P1 * P1), rem = j % (P1 * P1);
            sIn[icl * (P1 * 30) + (rem / P1) * 30 + (rem % P1)] =
                in[(s * 5 + icl) * (P1 * P1) + rem];
        }
        __syncthreads();
        if (!active) continue;

        for (int icl = 0; icl < 5; ++icl) {
            int ic = s * 5 + icl;
            for (int ky = 0; ky < 7; ++ky) {
                const float* rp0 = &sIn[icl * (P1 * 30) + (2 * oy + ky) * 30 + 2 * ox];
                const float* rp1 = rp0 + 30;
                float2 A0 = *(const float2*)(rp0 + 0);
                float2 A1 = *(const float2*)(rp0 + 2);
                float2 A2 = *(const float2*)(rp0 + 4);
                float2 A3 = *(const float2*)(rp0 + 6);
                float2 B0 = *(const float2*)(rp1 + 0);
                float2 B1 = *(const float2*)(rp1 + 2);
                float2 B2 = *(const float2*)(rp1 + 4);
                float2 B3 = *(const float2*)(rp1 + 6);
                u64 d0[8], d1[8];
                d0[0]=dup2(A0.x); d0[1]=dup2(A0.y); d0[2]=dup2(A1.x); d0[3]=dup2(A1.y);
                d0[4]=dup2(A2.x); d0[5]=dup2(A2.y); d0[6]=dup2(A3.x); d0[7]=dup2(A3.y);
                d1[0]=dup2(B0.x); d1[1]=dup2(B0.y); d1[2]=dup2(B1.x); d1[3]=dup2(B1.y);
                d1[4]=dup2(B2.x); d1[5]=dup2(B2.y); d1[6]=dup2(B3.x); d1[7]=dup2(B3.y);
                #pragma unroll
                for (int p = 0; p < 3; ++p) {
                    const float2* wr = &sW2[p * (C1 * 49) + ic * 49 + ky * 7];
                    #pragma unroll
                    for (int kx = 0; kx < 7; ++kx) {
                        u64 wv = *(const u64*)(wr + kx);
                        acc[p][0] = ffma2(d0[kx],     wv, acc[p][0]);
                        acc[p][1] = ffma2(d0[kx + 1], wv, acc[p][1]);
                        acc[p][2] = ffma2(d1[kx],     wv, acc[p][2]);
                        acc[p][3] = ffma2(d1[kx + 1], wv, acc[p][3]);
                    }
                }
            }
        }
    }

    if (active) {
        float* ob = out + (size_t)b * C2 * P2 * P2 + oc0 * (P2 * P2) + tid;
        #pragma unroll
        for (int p = 0; p < 3; ++p) {
            float2 v0 = unpack2(acc[p][0]);
            float2 v1 = unpack2(acc[p][1]);
            float2 v2 = unpack2(acc[p][2]);
            float2 v3 = unpack2(acc[p][3]);
            float sa = sScale[2 * p],     ba = sBias[2 * p];
            float sb = sScale[2 * p + 1], bb = sBias[2 * p + 1];
            float mA = fmaxf(fmaxf(v0.x * sa + ba, v1.x * sa + ba),
                             fmaxf(v2.x * sa + ba, v3.x * sa + ba));
            float mB = fmaxf(fmaxf(v0.y * sb + bb, v1.y * sb + bb),
                             fmaxf(v2.y * sb + bb, v3.y * sb + bb));
            ob[(2 * p)     * (P2 * P2)] = fmaxf(mA, 0.f);
            ob[(2 * p + 1) * (P2 * P2)] = fmaxf(mB, 0.f);
        }
    }
}

// ---------------- FC1: [2048,3630] x [200,3630]^T + bias, ReLU --------------
// 64x64 register tile, 4x4 per thread, n-paired FFMA2.
__global__ void __launch_bounds__(256)
fc1_kernel(const float* __restrict__ A,
           const float* __restrict__ W,
           const float* __restrict__ bias,
           float* __restrict__ out) {
    __shared__ __align__(16) float sA[16][64];
    __shared__ __align__(16) float sW[16][64];

    const int tx = threadIdx.x, ty = threadIdx.y;     // 16x16
    const int t  = ty * 16 + tx;
    const int by = blockIdx.y, bx = blockIdx.x;

    u64 acc[4][2];
    #pragma unroll
    for (int i = 0; i < 4; ++i) { acc[i][0] = 0ULL; acc[i][1] = 0ULL; }

    const int mrow0 = by * 64;
    const int nrow0 = bx * 64;
    const int kp = t % 8;             // which k-pair (0..7) this thread loads

    for (int k0 = 0; k0 < FC1IN; k0 += 16) {
        int gk = k0 + 2 * kp;
        bool kok = gk < FC1IN;        // FC1IN even, pairs all-or-nothing
        #pragma unroll
        for (int h = 0; h < 2; ++h) {
            int m = t / 8 + 32 * h;
            float2 va = kok ? *(const float2*)&A[(size_t)(mrow0 + m) * FC1IN + gk]
                            : make_float2(0.f, 0.f);
            sA[2 * kp][m]     = va.x;
            sA[2 * kp + 1][m] = va.y;
            int n = nrow0 + t / 8 + 32 * h;
            float2 vw = (kok && n < FC1OUT)
                        ? *(const float2*)&W[(size_t)n * FC1IN + gk]
                        : make_float2(0.f, 0.f);
            sW[2 * kp][t / 8 + 32 * h]     = vw.x;
            sW[2 * kp + 1][t / 8 + 32 * h] = vw.y;
        }
        __syncthreads();
        #pragma unroll
        for (int kk = 0; kk < 16; ++kk) {
            float4 a4 = *(const float4*)&sA[kk][ty * 4];
            u64 w01 = *(const u64*)&sW[kk][tx * 4];
            u64 w23 = *(const u64*)&sW[kk][tx * 4 + 2];
            u64 a0 = dup2(a4.x), a1 = dup2(a4.y), a2 = dup2(a4.z), a3 = dup2(a4.w);
            acc[0][0] = ffma2(a0, w01, acc[0][0]); acc[0][1] = ffma2(a0, w23, acc[0][1]);
            acc[1][0] = ffma2(a1, w01, acc[1][0]); acc[1][1] = ffma2(a1, w23, acc[1][1]);
            acc[2][0] = ffma2(a2, w01, acc[2][0]); acc[2][1] = ffma2(a2, w23, acc[2][1]);
            acc[3][0] = ffma2(a3, w01, acc[3][0]); acc[3][1] = ffma2(a3, w23, acc[3][1]);
        }
        __syncthreads();
    }

    const int n0 = nrow0 + tx * 4;
    #pragma unroll
    for (int i = 0; i < 4; ++i) {
        int m = mrow0 + ty * 4 + i;
        float2 vA = unpack2(acc[i][0]);
        float2 vB = unpack2(acc[i][1]);
        float* orow = out + (size_t)m * FC1OUT;
        if (n0     < FC1OUT) orow[n0]     = fmaxf(vA.x + bias[n0],     0.f);
        if (n0 + 1 < FC1OUT) orow[n0 + 1] = fmaxf(vA.y + bias[n0 + 1], 0.f);
        if (n0 + 2 < FC1OUT) orow[n0 + 2] = fmaxf(vB.x + bias[n0 + 2], 0.f);
        if (n0 + 3 < FC1OUT) orow[n0 + 3] = fmaxf(vB.y + bias[n0 + 3], 0.f);
    }
}

// ---------------- FC2 + sigmoid ----------------
__global__ void fc2_kernel(const float* __restrict__ A,
                           const float* __restrict__ W,
                           const float* __restrict__ bias,
                           float* __restrict__ out) {
    int idx = blockIdx.x * blockDim.x + threadIdx.x;  // b*2 + n
    if (idx >= B_SZ * FC2OUT) return;
    int b = idx >> 1, n = idx & 1;
    const float* a  = A + (size_t)b * FC1OUT;
    const float* wr = W + (size_t)n * FC1OUT;
    float acc = bias[n];
    #pragma unroll 8
    for (int k = 0; k < FC1OUT; ++k)
        acc = fmaf(a[k], wr[k], acc);
    out[idx] = 1.f / (1.f + expf(-acc));
}

// ---------------- launch ----------------
extern "C" void kernel_launch(void* const* d_in, const int* in_sizes, int n_in,
                              void* d_out, int out_size) {
    const float* x     = (const float*)d_in[0];
    const float* log_s = (const float*)d_in[1];
    const float* log_a = (const float*)d_in[2];
    const float* log_d = (const float*)d_in[3];
    const float* log_r = (const float*)d_in[4];
    const float* c1w   = (const float*)d_in[5];
    const float* c1b   = (const float*)d_in[6];
    const float* bn1g  = (const float*)d_in[7];
    const float* bn1b  = (const float*)d_in[8];
    const float* bn1m  = (const float*)d_in[9];
    const float* bn1v  = (const float*)d_in[10];
    const float* c2w   = (const float*)d_in[11];
    const float* c2b   = (const float*)d_in[12];
    const float* bn2g  = (const float*)d_in[13];
    const float* bn2b  = (const float*)d_in[14];
    const float* bn2m  = (const float*)d_in[15];
    const float* bn2v  = (const float*)d_in[16];
    const float* fc1w  = (const float*)d_in[17];
    const float* fc1b  = (const float*)d_in[18];
    const float* fc2w  = (const float*)d_in[19];
    const float* fc2b  = (const float*)d_in[20];
    float* out = (float*)d_out;

    float* pcen;  cudaGetSymbolAddress((void**)&pcen,  g_pcen);
    float* pool1; cudaGetSymbolAddress((void**)&pool1, g_pool1);
    float* pool2; cudaGetSymbolAddress((void**)&pool2, g_pool2);
    float* fc1o;  cudaGetSymbolAddress((void**)&fc1o,  g_fc1);

    pcen_kernel<<<(B_SZ * HW + 255) / 256, 256>>>(x, log_s, log_a, log_d, log_r, pcen);

    conv1_kernel<<<dim3(B_SZ, 2), 256>>>(pcen, c1w, c1b, bn1g, bn1b, bn1m, bn1v, pool1);

    conv2_kernel<<<dim3(B_SZ, 5), 128>>>(pool1, c2w, c2b, bn2g, bn2b, bn2m, bn2v, pool2);

    fc1_kernel<<<dim3((FC1OUT + 63) / 64, B_SZ / 64), dim3(16, 16)>>>(pool2, fc1w, fc1b, fc1o);

    fc2_kernel<<<(B_SZ * FC2OUT + 255) / 256, 256>>>(fc1o, fc2w, fc2b, out);
}

// round 3
// speedup vs baseline: 1.9933x; 1.4494x over previous
#include <cuda_runtime.h>
#include <math.h>

#define B_SZ   2048
#define HW     64
#define C1     15
#define C2     30
#define P1     29          // pooled1 spatial (58/2)
#define P2     11          // pooled2 spatial (23/2 floor)
#define FC1IN  (C2*P2*P2)  // 3630
#define FC1OUT 200
#define FC2OUT 2
#define KSPLIT 4

typedef unsigned long long u64;

// ---------------- f32x2 packed helpers (Blackwell FFMA2) ----------------
__device__ __forceinline__ u64 ffma2(u64 a, u64 b, u64 c) {
    u64 d;
    asm("fma.rn.f32x2 %0, %1, %2, %3;" : "=l"(d) : "l"(a), "l"(b), "l"(c));
    return d;
}
__device__ __forceinline__ u64 pack2(float lo, float hi) {
    u64 d;
    asm("mov.b64 %0, {%1, %2};" : "=l"(d) : "f"(lo), "f"(hi));
    return d;
}
__device__ __forceinline__ u64 dup2(float v) { return pack2(v, v); }
__device__ __forceinline__ float2 unpack2(u64 v) {
    float2 r;
    asm("mov.b64 {%0, %1}, %2;" : "=f"(r.x), "=f"(r.y) : "l"(v));
    return r;
}
__device__ __forceinline__ float fex2(float x) {
    float y; asm("ex2.approx.f32 %0, %1;" : "=f"(y) : "f"(x)); return y;
}
__device__ __forceinline__ float flg2(float x) {
    float y; asm("lg2.approx.f32 %0, %1;" : "=f"(y) : "f"(x)); return y;
}

// ---------------- scratch (static device allocations) ----------------
__device__ float g_pcen [B_SZ * HW * HW];            // [B,64,64]
__device__ float g_pool1[B_SZ * C1 * P1 * P1];       // [B,15,29,29]
__device__ float g_pool2[B_SZ * C2 * P2 * P2];       // [B,30,11,11]
__device__ float g_fc1p [KSPLIT * B_SZ * FC1OUT];    // split-K partials
__device__ float g_fc1  [B_SZ * FC1OUT];             // [B,200]

// ---------------- PCEN: EMA over W per (b,h) row ----------------
__global__ void pcen_kernel(const float* __restrict__ x,
                            const float* __restrict__ log_s,
                            const float* __restrict__ log_alpha,
                            const float* __restrict__ log_delta,
                            const float* __restrict__ log_r,
                            float* __restrict__ out) {
    int idx = blockIdx.x * blockDim.x + threadIdx.x;   // b*64 + h
    if (idx >= B_SZ * HW) return;
    const float s     = expf(log_s[0]);
    const float alpha = expf(log_alpha[0]);
    const float delta = expf(log_delta[0]);
    const float r     = expf(log_r[0]);
    const float dr    = fex2(r * flg2(delta));
    const float* row  = x   + (size_t)idx * HW;
    float*       orow = out + (size_t)idx * HW;
    float m = 0.f;
    #pragma unroll 8
    for (int w = 0; w < HW; ++w) {
        float v = __ldg(row + w);
        m = (1.f - s) * m + s * v;                      // m0 = s*x0 (m starts 0)
        float t = fmaf(v, fex2(-alpha * flg2(m + 1e-6f)), delta);
        orow[w] = fex2(r * flg2(t)) - dr;
    }
}

// ---------------- conv1 (1->15 padded to 16, 7x7) + BN + ReLU + maxpool2 ----
// grid (B, 2): blockIdx.y selects 4 oc-pairs (8 channels). Weights stored
// oc-pair interleaved (float2) so one broadcast LDS.64 feeds an FFMA2.
__global__ void __launch_bounds__(224, 2)
conv1_kernel(const float* __restrict__ pcen,
             const float* __restrict__ w,
             const float* __restrict__ cb,
             const float* __restrict__ g,
             const float* __restrict__ beta,
             const float* __restrict__ mean,
             const float* __restrict__ var,
             float* __restrict__ out) {
    __shared__ __align__(16) float  sIn[HW * HW];   // 16 KB
    __shared__ __align__(16) float2 sW2[4 * 49];    // 4 pairs x 49 taps
    __shared__ float sScale[8], sBias[8];

    const int b     = blockIdx.x;
    const int group = blockIdx.y;      // pairs group*4 .. group*4+3
    const int tid   = threadIdx.x;

    const float* in = pcen + (size_t)b * HW * HW;
    for (int i = tid; i < HW * HW; i += 224) sIn[i] = in[i];
    for (int j = tid; j < 4 * 49; j += 224) {
        int p  = j / 49, t = j % 49;
        int oa = (group * 4 + p) * 2;
        int ob = oa + 1;
        float wa = w[oa * 49 + t];
        float wb = (ob < C1) ? w[ob * 49 + t] : 0.f;
        sW2[j] = make_float2(wa, wb);
    }
    if (tid < 8) {
        int oc = group * 8 + tid;
        if (oc < C1) {
            float inv = g[oc] * rsqrtf(var[oc] + 1e-5f);
            sScale[tid] = inv;
            sBias[tid]  = cb[oc] * inv + beta[oc] - mean[oc] * inv;
        } else { sScale[tid] = 0.f; sBias[tid] = 0.f; }
    }
    __syncthreads();

    float* ob_base = out + (size_t)b * C1 * P1 * P1;

    for (int cell = tid; cell < P1 * P1; cell += 224) {
        int oy = cell / P1, ox = cell % P1;
        u64 acc[4][4];
        #pragma unroll
        for (int p = 0; p < 4; ++p)
            #pragma unroll
            for (int q = 0; q < 4; ++q) acc[p][q] = 0ULL;

        #pragma unroll
        for (int ky = 0; ky < 7; ++ky) {
            const float* rp0 = &sIn[(2 * oy + ky) * HW + 2 * ox];
            const float* rp1 = rp0 + HW;
            float2 A0 = *(const float2*)(rp0 + 0);
            float2 A1 = *(const float2*)(rp0 + 2);
            float2 A2 = *(const float2*)(rp0 + 4);
            float2 A3 = *(const float2*)(rp0 + 6);
            float2 B0 = *(const float2*)(rp1 + 0);
            float2 B1 = *(const float2*)(rp1 + 2);
            float2 B2 = *(const float2*)(rp1 + 4);
            float2 B3 = *(const float2*)(rp1 + 6);
            u64 d0[8], d1[8];
            d0[0]=dup2(A0.x); d0[1]=dup2(A0.y); d0[2]=dup2(A1.x); d0[3]=dup2(A1.y);
            d0[4]=dup2(A2.x); d0[5]=dup2(A2.y); d0[6]=dup2(A3.x); d0[7]=dup2(A3.y);
            d1[0]=dup2(B0.x); d1[1]=dup2(B0.y); d1[2]=dup2(B1.x); d1[3]=dup2(B1.y);
            d1[4]=dup2(B2.x); d1[5]=dup2(B2.y); d1[6]=dup2(B3.x); d1[7]=dup2(B3.y);
            #pragma unroll
            for (int p = 0; p < 4; ++p) {
                const float2* wr = &sW2[p * 49 + ky * 7];
                #pragma unroll
                for (int kx = 0; kx < 7; ++kx) {
                    u64 wv = *(const u64*)(wr + kx);
                    acc[p][0] = ffma2(d0[kx],     wv, acc[p][0]);
                    acc[p][1] = ffma2(d0[kx + 1], wv, acc[p][1]);
                    acc[p][2] = ffma2(d1[kx],     wv, acc[p][2]);
                    acc[p][3] = ffma2(d1[kx + 1], wv, acc[p][3]);
                }
            }
        }

        #pragma unroll
        for (int p = 0; p < 4; ++p) {
            float2 v0 = unpack2(acc[p][0]);
            float2 v1 = unpack2(acc[p][1]);
            float2 v2 = unpack2(acc[p][2]);
            float2 v3 = unpack2(acc[p][3]);
            int la = 2 * p, lb = 2 * p + 1;
            int oa = group * 8 + la, obc = group * 8 + lb;
            float sa = sScale[la], ba = sBias[la];
            float mA = fmaxf(fmaxf(v0.x * sa + ba, v1.x * sa + ba),
                             fmaxf(v2.x * sa + ba, v3.x * sa + ba));
            ob_base[oa * (P1 * P1) + cell] = fmaxf(mA, 0.f);
            if (obc < C1) {
                float sb = sScale[lb], bb = sBias[lb];
                float mB = fmaxf(fmaxf(v0.y * sb + bb, v1.y * sb + bb),
                                 fmaxf(v2.y * sb + bb, v3.y * sb + bb));
                ob_base[obc * (P1 * P1) + cell] = fmaxf(mB, 0.f);
            }
        }
    }
}

// ---------------- conv2 (15->30, 7x7) + BN + ReLU + maxpool2 ----------------
// grid (B, 3): each block does 10 output channels (5 FFMA2 pairs) for one
// image. Input streamed in 3-ic slabs (rows padded to 30 for aligned float2).
__global__ void __launch_bounds__(128, 4)
conv2_kernel(const float* __restrict__ pool1,
             const float* __restrict__ w,
             const float* __restrict__ cb,
             const float* __restrict__ g,
             const float* __restrict__ beta,
             const float* __restrict__ mean,
             const float* __restrict__ var,
             float* __restrict__ out) {
    __shared__ __align__(16) float  sIn[3 * P1 * 30];   // 3 ic x 29 x 30 pad
    __shared__ __align__(16) float2 sW2[5 * C1 * 49];   // 5 pairs x 735
    __shared__ float sScale[10], sBias[10];

    const int b   = blockIdx.x;
    const int oc0 = blockIdx.y * 10;
    const int tid = threadIdx.x;

    for (int j = tid; j < 5 * C1 * 49; j += 128) {
        int p = j / (C1 * 49), t = j % (C1 * 49);
        sW2[j] = make_float2(w[(oc0 + 2 * p)     * (C1 * 49) + t],
                             w[(oc0 + 2 * p + 1) * (C1 * 49) + t]);
    }
    if (tid < 10) {
        int oc = oc0 + tid;
        float inv = g[oc] * rsqrtf(var[oc] + 1e-5f);
        sScale[tid] = inv;
        sBias[tid]  = cb[oc] * inv + beta[oc] - mean[oc] * inv;
    }

    const float* in = pool1 + (size_t)b * C1 * P1 * P1;
    const int oy = tid / P2, ox = tid % P2;
    const bool active = tid < P2 * P2;

    u64 acc[5][4];
    #pragma unroll
    for (int p = 0; p < 5; ++p)
        #pragma unroll
        for (int q = 0; q < 4; ++q) acc[p][q] = 0ULL;

    for (int s = 0; s < 5; ++s) {
        __syncthreads();
        for (int j = tid; j < 3 * P1 * P1; j += 128) {
            int icl = j / (P1 * P1), rem = j % (P1 * P1);
            sIn[icl * (P1 * 30) + (rem / P1) * 30 + (rem % P1)] =
                in[(s * 3 + icl) * (P1 * P1) + rem];
        }
        __syncthreads();
        if (!active) continue;

        #pragma unroll
        for (int icl = 0; icl < 3; ++icl) {
            int ic = s * 3 + icl;
            #pragma unroll
            for (int ky = 0; ky < 7; ++ky) {
                const float* rp0 = &sIn[icl * (P1 * 30) + (2 * oy + ky) * 30 + 2 * ox];
                const float* rp1 = rp0 + 30;
                float2 A0 = *(const float2*)(rp0 + 0);
                float2 A1 = *(const float2*)(rp0 + 2);
                float2 A2 = *(const float2*)(rp0 + 4);
                float2 A3 = *(const float2*)(rp0 + 6);
                float2 B0 = *(const float2*)(rp1 + 0);
                float2 B1 = *(const float2*)(rp1 + 2);
                float2 B2 = *(const float2*)(rp1 + 4);
                float2 B3 = *(const float2*)(rp1 + 6);
                float in0[8] = {A0.x, A0.y, A1.x, A1.y, A2.x, A2.y, A3.x, A3.y};
                float in1[8] = {B0.x, B0.y, B1.x, B1.y, B2.x, B2.y, B3.x, B3.y};
                const float2* wr = &sW2[ic * 49 + ky * 7];
                #pragma unroll
                for (int kx = 0; kx < 7; ++kx) {
                    u64 da = dup2(in0[kx]);
                    u64 db = dup2(in0[kx + 1]);
                    u64 dc = dup2(in1[kx]);
                    u64 dd = dup2(in1[kx + 1]);
                    #pragma unroll
                    for (int p = 0; p < 5; ++p) {
                        u64 wv = *(const u64*)(wr + p * (C1 * 49) + kx);
                        acc[p][0] = ffma2(da, wv, acc[p][0]);
                        acc[p][1] = ffma2(db, wv, acc[p][1]);
                        acc[p][2] = ffma2(dc, wv, acc[p][2]);
                        acc[p][3] = ffma2(dd, wv, acc[p][3]);
                    }
                }
            }
        }
    }

    if (active) {
        float* ob = out + (size_t)b * C2 * P2 * P2 + oc0 * (P2 * P2) + tid;
        #pragma unroll
        for (int p = 0; p < 5; ++p) {
            float2 v0 = unpack2(acc[p][0]);
            float2 v1 = unpack2(acc[p][1]);
            float2 v2 = unpack2(acc[p][2]);
            float2 v3 = unpack2(acc[p][3]);
            float sa = sScale[2 * p],     ba = sBias[2 * p];
            float sb = sScale[2 * p + 1], bb = sBias[2 * p + 1];
            float mA = fmaxf(fmaxf(v0.x * sa + ba, v1.x * sa + ba),
                             fmaxf(v2.x * sa + ba, v3.x * sa + ba));
            float mB = fmaxf(fmaxf(v0.y * sb + bb, v1.y * sb + bb),
                             fmaxf(v2.y * sb + bb, v3.y * sb + bb));
            ob[(2 * p)     * (P2 * P2)] = fmaxf(mA, 0.f);
            ob[(2 * p + 1) * (P2 * P2)] = fmaxf(mB, 0.f);
        }
    }
}

// ---------------- FC1 split-K partial: 64x64 tile, 4x4/thread, FFMA2 --------
__global__ void __launch_bounds__(256)
fc1_partial_kernel(const float* __restrict__ A,
                   const float* __restrict__ W,
                   float* __restrict__ partial) {
    __shared__ __align__(16) float sA[16][64];
    __shared__ __align__(16) float sW[16][64];

    const int tx = threadIdx.x, ty = threadIdx.y;     // 16x16
    const int t  = ty * 16 + tx;
    const int by = blockIdx.y, bx = blockIdx.x, kz = blockIdx.z;

    const int kchunk = (FC1IN + KSPLIT - 1) / KSPLIT;  // 908
    const int kbeg = kz * kchunk;
    const int kend = (kbeg + kchunk < FC1IN) ? (kbeg + kchunk) : FC1IN;

    u64 acc[4][2];
    #pragma unroll
    for (int i = 0; i < 4; ++i) { acc[i][0] = 0ULL; acc[i][1] = 0ULL; }

    const int mrow0 = by * 64;
    const int nrow0 = bx * 64;
    const int kp = t % 8;             // which k-pair (0..7) this thread loads

    for (int k0 = kbeg; k0 < kend; k0 += 16) {
        int gk = k0 + 2 * kp;
        bool kok = gk < kend;         // pairs never straddle (kend even)
        #pragma unroll
        for (int h = 0; h < 2; ++h) {
            int m = t / 8 + 32 * h;
            float2 va = kok ? *(const float2*)&A[(size_t)(mrow0 + m) * FC1IN + gk]
                            : make_float2(0.f, 0.f);
            sA[2 * kp][m]     = va.x;
            sA[2 * kp + 1][m] = va.y;
            int n = nrow0 + t / 8 + 32 * h;
            float2 vw = (kok && n < FC1OUT)
                        ? *(const float2*)&W[(size_t)n * FC1IN + gk]
                        : make_float2(0.f, 0.f);
            sW[2 * kp][t / 8 + 32 * h]     = vw.x;
            sW[2 * kp + 1][t / 8 + 32 * h] = vw.y;
        }
        __syncthreads();
        #pragma unroll
        for (int kk = 0; kk < 16; ++kk) {
            float4 a4 = *(const float4*)&sA[kk][ty * 4];
            u64 w01 = *(const u64*)&sW[kk][tx * 4];
            u64 w23 = *(const u64*)&sW[kk][tx * 4 + 2];
            u64 a0 = dup2(a4.x), a1 = dup2(a4.y), a2 = dup2(a4.z), a3 = dup2(a4.w);
            acc[0][0] = ffma2(a0, w01, acc[0][0]); acc[0][1] = ffma2(a0, w23, acc[0][1]);
            acc[1][0] = ffma2(a1, w01, acc[1][0]); acc[1][1] = ffma2(a1, w23, acc[1][1]);
            acc[2][0] = ffma2(a2, w01, acc[2][0]); acc[2][1] = ffma2(a2, w23, acc[2][1]);
            acc[3][0] = ffma2(a3, w01, acc[3][0]); acc[3][1] = ffma2(a3, w23, acc[3][1]);
        }
        __syncthreads();
    }

    float* pbase = partial + (size_t)kz * B_SZ * FC1OUT;
    const int n0 = nrow0 + tx * 4;
    #pragma unroll
    for (int i = 0; i < 4; ++i) {
        int m = mrow0 + ty * 4 + i;
        float2 vA = unpack2(acc[i][0]);
        float2 vB = unpack2(acc[i][1]);
        float* orow = pbase + (size_t)m * FC1OUT;
        if (n0     < FC1OUT) orow[n0]     = vA.x;
        if (n0 + 1 < FC1OUT) orow[n0 + 1] = vA.y;
        if (n0 + 2 < FC1OUT) orow[n0 + 2] = vB.x;
        if (n0 + 3 < FC1OUT) orow[n0 + 3] = vB.y;
    }
}

// ---------------- FC1 reduce: sum split-K partials + bias + ReLU ------------
__global__ void fc1_reduce_kernel(const float* __restrict__ partial,
                                  const float* __restrict__ bias,
                                  float* __restrict__ out) {
    int idx = blockIdx.x * blockDim.x + threadIdx.x;
    if (idx >= B_SZ * FC1OUT) return;
    int n = idx % FC1OUT;
    float v = bias[n];
    #pragma unroll
    for (int z = 0; z < KSPLIT; ++z)
        v += partial[(size_t)z * B_SZ * FC1OUT + idx];
    out[idx] = fmaxf(v, 0.f);
}

// ---------------- FC2 + sigmoid ----------------
__global__ void fc2_kernel(const float* __restrict__ A,
                           const float* __restrict__ W,
                           const float* __restrict__ bias,
                           float* __restrict__ out) {
    int idx = blockIdx.x * blockDim.x + threadIdx.x;  // b*2 + n
    if (idx >= B_SZ * FC2OUT) return;
    int b = idx >> 1, n = idx & 1;
    const float* a  = A + (size_t)b * FC1OUT;
    const float* wr = W + (size_t)n * FC1OUT;
    float acc = bias[n];
    #pragma unroll 8
    for (int k = 0; k < FC1OUT; ++k)
        acc = fmaf(a[k], wr[k], acc);
    out[idx] = 1.f / (1.f + expf(-acc));
}

// ---------------- launch ----------------
extern "C" void kernel_launch(void* const* d_in, const int* in_sizes, int n_in,
                              void* d_out, int out_size) {
    const float* x     = (const float*)d_in[0];
    const float* log_s = (const float*)d_in[1];
    const float* log_a = (const float*)d_in[2];
    const float* log_d = (const float*)d_in[3];
    const float* log_r = (const float*)d_in[4];
    const float* c1w   = (const float*)d_in[5];
    const float* c1b   = (const float*)d_in[6];
    const float* bn1g  = (const float*)d_in[7];
    const float* bn1b  = (const float*)d_in[8];
    const float* bn1m  = (const float*)d_in[9];
    const float* bn1v  = (const float*)d_in[10];
    const float* c2w   = (const float*)d_in[11];
    const float* c2b   = (const float*)d_in[12];
    const float* bn2g  = (const float*)d_in[13];
    const float* bn2b  = (const float*)d_in[14];
    const float* bn2m  = (const float*)d_in[15];
    const float* bn2v  = (const float*)d_in[16];
    const float* fc1w  = (const float*)d_in[17];
    const float* fc1b  = (const float*)d_in[18];
    const float* fc2w  = (const float*)d_in[19];
    const float* fc2b  = (const float*)d_in[20];
    float* out = (float*)d_out;

    float* pcen;  cudaGetSymbolAddress((void**)&pcen,  g_pcen);
    float* pool1; cudaGetSymbolAddress((void**)&pool1, g_pool1);
    float* pool2; cudaGetSymbolAddress((void**)&pool2, g_pool2);
    float* fc1p;  cudaGetSymbolAddress((void**)&fc1p,  g_fc1p);
    float* fc1o;  cudaGetSymbolAddress((void**)&fc1o,  g_fc1);

    pcen_kernel<<<(B_SZ * HW + 255) / 256, 256>>>(x, log_s, log_a, log_d, log_r, pcen);

    conv1_kernel<<<dim3(B_SZ, 2), 224>>>(pcen, c1w, c1b, bn1g, bn1b, bn1m, bn1v, pool1);

    conv2_kernel<<<dim3(B_SZ, 3), 128>>>(pool1, c2w, c2b, bn2g, bn2b, bn2m, bn2v, pool2);

    fc1_partial_kernel<<<dim3((FC1OUT + 63) / 64, B_SZ / 64, KSPLIT), dim3(16, 16)>>>(
        pool2, fc1w, fc1p);

    fc1_reduce_kernel<<<(B_SZ * FC1OUT + 255) / 256, 256>>>(fc1p, fc1b, fc1o);

    fc2_kernel<<<(B_SZ * FC2OUT + 255) / 256, 256>>>(fc1o, fc2w, fc2b, out);
}

// round 4
// speedup vs baseline: 2.2321x; 1.1198x over previous
#include <cuda_runtime.h>
#include <math.h>
#include <stdint.h>

#define B_SZ   2048
#define HW     64
#define C1     15
#define C2     30
#define P1     29          // pooled1 spatial (58/2)
#define P2     11          // pooled2 spatial (23/2 floor)
#define FC1IN  (C2*P2*P2)  // 3630
#define FC1OUT 200
#define FC2OUT 2
#define KSPLIT 4

// conv2-mma geometry
#define POS    484         // 22*22 conv positions needed for 11x11 pool
#define POSP   512         // padded to 8 warps * 64
#define NSTEPS 105         // 15 ic * 7 ksteps (49 taps padded to 56)

typedef unsigned long long u64;

// ---------------- f32x2 packed helpers (Blackwell FFMA2) ----------------
__device__ __forceinline__ u64 ffma2(u64 a, u64 b, u64 c) {
    u64 d;
    asm("fma.rn.f32x2 %0, %1, %2, %3;" : "=l"(d) : "l"(a), "l"(b), "l"(c));
    return d;
}
__device__ __forceinline__ u64 pack2(float lo, float hi) {
    u64 d;
    asm("mov.b64 %0, {%1, %2};" : "=l"(d) : "f"(lo), "f"(hi));
    return d;
}
__device__ __forceinline__ u64 dup2(float v) { return pack2(v, v); }
__device__ __forceinline__ float2 unpack2(u64 v) {
    float2 r;
    asm("mov.b64 {%0, %1}, %2;" : "=f"(r.x), "=f"(r.y) : "l"(v));
    return r;
}
__device__ __forceinline__ float fex2(float x) {
    float y; asm("ex2.approx.f32 %0, %1;" : "=f"(y) : "f"(x)); return y;
}
__device__ __forceinline__ float flg2(float x) {
    float y; asm("lg2.approx.f32 %0, %1;" : "=f"(y) : "f"(x)); return y;
}
// round fp32 -> tf32 (kept in a 32-bit float container)
__device__ __forceinline__ float cvt_tf32(float x) {
    uint32_t u;
    asm("cvt.rna.tf32.f32 %0, %1;" : "=r"(u) : "f"(x));
    return __uint_as_float(u);
}
// m16n8k8 tf32 MMA, fp32 accumulate
__device__ __forceinline__ void mma_tf32(float& c0, float& c1, float& c2, float& c3,
                                         uint32_t a0, uint32_t a1, uint32_t a2, uint32_t a3,
                                         uint32_t b0, uint32_t b1) {
    asm volatile(
        "mma.sync.aligned.m16n8k8.row.col.f32.tf32.tf32.f32 "
        "{%0,%1,%2,%3}, {%4,%5,%6,%7}, {%8,%9}, {%0,%1,%2,%3};"
        : "+f"(c0), "+f"(c1), "+f"(c2), "+f"(c3)
        : "r"(a0), "r"(a1), "r"(a2), "r"(a3), "r"(b0), "r"(b1));
}

// ---------------- scratch (static device allocations) ----------------
__device__ float g_pcen [B_SZ * HW * HW];            // [B,64,64]
__device__ float g_pool1[B_SZ * C1 * P1 * P1];       // [B,15,29,29]
__device__ float g_pool2[B_SZ * C2 * P2 * P2];       // [B,30,11,11]
__device__ float g_fc1p [KSPLIT * B_SZ * FC1OUT];    // split-K partials
__device__ float g_fc1  [B_SZ * FC1OUT];             // [B,200]

// ---------------- PCEN: EMA over W per (b,h) row ----------------
__global__ void pcen_kernel(const float* __restrict__ x,
                            const float* __restrict__ log_s,
                            const float* __restrict__ log_alpha,
                            const float* __restrict__ log_delta,
                            const float* __restrict__ log_r,
                            float* __restrict__ out) {
    int idx = blockIdx.x * blockDim.x + threadIdx.x;   // b*64 + h
    if (idx >= B_SZ * HW) return;
    const float s     = expf(log_s[0]);
    const float alpha = expf(log_alpha[0]);
    const float delta = expf(log_delta[0]);
    const float r     = expf(log_r[0]);
    const float dr    = fex2(r * flg2(delta));
    const float* row  = x   + (size_t)idx * HW;
    float*       orow = out + (size_t)idx * HW;
    float m = 0.f;
    #pragma unroll 8
    for (int w = 0; w < HW; ++w) {
        float v = __ldg(row + w);
        m = (1.f - s) * m + s * v;                      // m0 = s*x0 (m starts 0)
        float t = fmaf(v, fex2(-alpha * flg2(m + 1e-6f)), delta);
        orow[w] = fex2(r * flg2(t)) - dr;
    }
}

// ---------------- conv1 (1->15 padded to 16, 7x7) + BN + ReLU + maxpool2 ----
__global__ void __launch_bounds__(224, 2)
conv1_kernel(const float* __restrict__ pcen,
             const float* __restrict__ w,
             const float* __restrict__ cb,
             const float* __restrict__ g,
             const float* __restrict__ beta,
             const float* __restrict__ mean,
             const float* __restrict__ var,
             float* __restrict__ out) {
    __shared__ __align__(16) float  sIn[HW * HW];   // 16 KB
    __shared__ __align__(16) float2 sW2[4 * 49];    // 4 pairs x 49 taps
    __shared__ float sScale[8], sBias[8];

    const int b     = blockIdx.x;
    const int group = blockIdx.y;      // pairs group*4 .. group*4+3
    const int tid   = threadIdx.x;

    const float* in = pcen + (size_t)b * HW * HW;
    for (int i = tid; i < HW * HW; i += 224) sIn[i] = in[i];
    for (int j = tid; j < 4 * 49; j += 224) {
        int p  = j / 49, t = j % 49;
        int oa = (group * 4 + p) * 2;
        int ob = oa + 1;
        float wa = w[oa * 49 + t];
        float wb = (ob < C1) ? w[ob * 49 + t] : 0.f;
        sW2[j] = make_float2(wa, wb);
    }
    if (tid < 8) {
        int oc = group * 8 + tid;
        if (oc < C1) {
            float inv = g[oc] * rsqrtf(var[oc] + 1e-5f);
            sScale[tid] = inv;
            sBias[tid]  = cb[oc] * inv + beta[oc] - mean[oc] * inv;
        } else { sScale[tid] = 0.f; sBias[tid] = 0.f; }
    }
    __syncthreads();

    float* ob_base = out + (size_t)b * C1 * P1 * P1;

    for (int cell = tid; cell < P1 * P1; cell += 224) {
        int oy = cell / P1, ox = cell % P1;
        u64 acc[4][4];
        #pragma unroll
        for (int p = 0; p < 4; ++p)
            #pragma unroll
            for (int q = 0; q < 4; ++q) acc[p][q] = 0ULL;

        #pragma unroll
        for (int ky = 0; ky < 7; ++ky) {
            const float* rp0 = &sIn[(2 * oy + ky) * HW + 2 * ox];
            const float* rp1 = rp0 + HW;
            float2 A0 = *(const float2*)(rp0 + 0);
            float2 A1 = *(const float2*)(rp0 + 2);
            float2 A2 = *(const float2*)(rp0 + 4);
            float2 A3 = *(const float2*)(rp0 + 6);
            float2 B0 = *(const float2*)(rp1 + 0);
            float2 B1 = *(const float2*)(rp1 + 2);
            float2 B2 = *(const float2*)(rp1 + 4);
            float2 B3 = *(const float2*)(rp1 + 6);
            u64 d0[8], d1[8];
            d0[0]=dup2(A0.x); d0[1]=dup2(A0.y); d0[2]=dup2(A1.x); d0[3]=dup2(A1.y);
            d0[4]=dup2(A2.x); d0[5]=dup2(A2.y); d0[6]=dup2(A3.x); d0[7]=dup2(A3.y);
            d1[0]=dup2(B0.x); d1[1]=dup2(B0.y); d1[2]=dup2(B1.x); d1[3]=dup2(B1.y);
            d1[4]=dup2(B2.x); d1[5]=dup2(B2.y); d1[6]=dup2(B3.x); d1[7]=dup2(B3.y);
            #pragma unroll
            for (int p = 0; p < 4; ++p) {
                const float2* wr = &sW2[p * 49 + ky * 7];
                #pragma unroll
                for (int kx = 0; kx < 7; ++kx) {
                    u64 wv = *(const u64*)(wr + kx);
                    acc[p][0] = ffma2(d0[kx],     wv, acc[p][0]);
                    acc[p][1] = ffma2(d0[kx + 1], wv, acc[p][1]);
                    acc[p][2] = ffma2(d1[kx],     wv, acc[p][2]);
                    acc[p][3] = ffma2(d1[kx + 1], wv, acc[p][3]);
                }
            }
        }

        #pragma unroll
        for (int p = 0; p < 4; ++p) {
            float2 v0 = unpack2(acc[p][0]);
            float2 v1 = unpack2(acc[p][1]);
            float2 v2 = unpack2(acc[p][2]);
            float2 v3 = unpack2(acc[p][3]);
            int la = 2 * p, lb = 2 * p + 1;
            int oa = group * 8 + la, obc = group * 8 + lb;
            float sa = sScale[la], ba = sBias[la];
            float mA = fmaxf(fmaxf(v0.x * sa + ba, v1.x * sa + ba),
                             fmaxf(v2.x * sa + ba, v3.x * sa + ba));
            ob_base[oa * (P1 * P1) + cell] = fmaxf(mA, 0.f);
            if (obc < C1) {
                float sb = sScale[lb], bb = sBias[lb];
                float mB = fmaxf(fmaxf(v0.y * sb + bb, v1.y * sb + bb),
                                 fmaxf(v2.y * sb + bb, v3.y * sb + bb));
                ob_base[obc * (P1 * P1) + cell] = fmaxf(mB, 0.f);
            }
        }
    }
}

// ---------------- conv2 via mma.sync tf32 implicit GEMM ---------------------
// One CTA per image, 256 threads (8 warps). Each warp: 64 positions x 32 oc.
// A-frags gathered directly from resident smem input (no im2col build).
// K = 15 ic * 49 taps, padded per-ic to 56 (7 ksteps of 8).
// smem: sIn [15][29][30] | offT[56] | scale/bias[32] | sW [105][32][8] (aliased
// by the 512x33 epilogue stage after the k-loop).
__global__ void __launch_bounds__(256, 1)
conv2_mma_kernel(const float* __restrict__ pool1,
                 const float* __restrict__ w,
                 const float* __restrict__ cb,
                 const float* __restrict__ g,
                 const float* __restrict__ beta,
                 const float* __restrict__ mean,
                 const float* __restrict__ var,
                 float* __restrict__ out) {
    extern __shared__ float smem[];
    float* sIn    = smem;                         // 13050 floats
    int*   offT   = (int*)(smem + 13050);         // 56
    float* sScale = smem + 13050 + 56;            // 32
    float* sBias  = sScale + 32;                  // 32
    float* sW     = sBias + 32;                   // 26880 floats
    float* sC     = sW;                           // alias (after k-loop)

    const int b    = blockIdx.x;
    const int tid  = threadIdx.x;
    const int warp = tid >> 5;
    const int lane = tid & 31;
    const int gq   = lane >> 2;     // group id 0..7
    const int tg   = lane & 3;      // thread-in-group 0..3

    if (tid < 56) offT[tid] = (tid < 49) ? (tid / 7) * 30 + (tid % 7) : 0;
    if (tid >= 64 && tid < 96) {
        int oc = tid - 64;
        if (oc < C2) {
            float inv = g[oc] * rsqrtf(var[oc] + 1e-5f);
            sScale[oc] = inv;
            sBias[oc]  = cb[oc] * inv + beta[oc] - mean[oc] * inv;
        } else { sScale[oc] = 0.f; sBias[oc] = 0.f; }
    }

    // input fill: [ic][row 0..28][col 0..29], col 29 zero-padded; tf32-rounded
    const float* in = pool1 + (size_t)b * C1 * (P1 * P1);
    for (int i = tid; i < C1 * 870; i += 256) {
        int ic = i / 870, rem = i % 870, row = rem / 30, col = rem % 30;
        float v = (col < P1) ? in[ic * (P1 * P1) + row * P1 + col] : 0.f;
        sIn[i] = cvt_tf32(v);
    }
    // weight fill: sW[s][oc 0..31][k 0..7]; zero-pad oc>=30 and kk>=49
    for (int i = tid; i < NSTEPS * 256; i += 256) {
        int s = i / 256, rem = i % 256, oc = rem / 8, k = rem % 8;
        int ic = s / 7, kk = (s % 7) * 8 + k;
        float v = (oc < C2 && kk < 49) ? w[oc * (C1 * 49) + ic * 49 + kk] : 0.f;
        sW[i] = cvt_tf32(v);
    }
    __syncthreads();

    // per-thread row bases for the 8 A-rows this thread touches
    int rb[4][2];
    #pragma unroll
    for (int mt = 0; mt < 4; ++mt) {
        #pragma unroll
        for (int h = 0; h < 2; ++h) {
            int r = warp * 64 + mt * 16 + gq + h * 8;
            rb[mt][h] = (r < POS) ? (r / 22) * 30 + (r % 22) : 0;
        }
    }

    float acc[4][4][4];
    #pragma unroll
    for (int mt = 0; mt < 4; ++mt)
        #pragma unroll
        for (int nt = 0; nt < 4; ++nt)
            #pragma unroll
            for (int q = 0; q < 4; ++q) acc[mt][nt][q] = 0.f;

    for (int ic = 0; ic < C1; ++ic) {
        const float* base = sIn + ic * 870;
        #pragma unroll
        for (int j = 0; j < 7; ++j) {
            const int s = ic * 7 + j;
            const int off0 = offT[j * 8 + tg];
            const int off1 = offT[j * 8 + tg + 4];
            // B fragments: sW[s][oc][k], oc = nt*8 + gq, k = tg / tg+4
            uint32_t bfr[4][2];
            const float* wS = sW + s * 256 + gq * 8;
            #pragma unroll
            for (int nt = 0; nt < 4; ++nt) {
                bfr[nt][0] = __float_as_uint(wS[nt * 64 + tg]);
                bfr[nt][1] = __float_as_uint(wS[nt * 64 + tg + 4]);
            }
            #pragma unroll
            for (int mt = 0; mt < 4; ++mt) {
                uint32_t a0 = __float_as_uint(base[rb[mt][0] + off0]);
                uint32_t a1 = __float_as_uint(base[rb[mt][1] + off0]);
                uint32_t a2 = __float_as_uint(base[rb[mt][0] + off1]);
                uint32_t a3 = __float_as_uint(base[rb[mt][1] + off1]);
                #pragma unroll
                for (int nt = 0; nt < 4; ++nt)
                    mma_tf32(acc[mt][nt][0], acc[mt][nt][1],
                             acc[mt][nt][2], acc[mt][nt][3],
                             a0, a1, a2, a3, bfr[nt][0], bfr[nt][1]);
            }
        }
    }
    __syncthreads();   // weights dead; reuse region as epilogue stage

    // stage scaled conv outputs: sC[pos][oc], stride 33 to dodge bank conflicts
    #pragma unroll
    for (int mt = 0; mt < 4; ++mt) {
        int pos0 = warp * 64 + mt * 16 + gq;
        #pragma unroll
        for (int nt = 0; nt < 4; ++nt) {
            int oc0 = nt * 8 + 2 * tg;
            float s0 = sScale[oc0],     b0v = sBias[oc0];
            float s1 = sScale[oc0 + 1], b1v = sBias[oc0 + 1];
            sC[pos0 * 33 + oc0]           = acc[mt][nt][0] * s0 + b0v;
            sC[pos0 * 33 + oc0 + 1]       = acc[mt][nt][1] * s1 + b1v;
            sC[(pos0 + 8) * 33 + oc0]     = acc[mt][nt][2] * s0 + b0v;
            sC[(pos0 + 8) * 33 + oc0 + 1] = acc[mt][nt][3] * s1 + b1v;
        }
    }
    __syncthreads();

    // 2x2 max-pool + ReLU -> g_pool2[b][oc][11][11]
    float* ob = out + (size_t)b * (C2 * P2 * P2);
    for (int i = tid; i < C2 * P2 * P2; i += 256) {
        int oc = i / (P2 * P2), cell = i % (P2 * P2);
        int oy = cell / P2, ox = cell % P2;
        int p = (2 * oy) * 22 + 2 * ox;
        float m0 = fmaxf(sC[p * 33 + oc],        sC[(p + 1) * 33 + oc]);
        float m1 = fmaxf(sC[(p + 22) * 33 + oc], sC[(p + 23) * 33 + oc]);
        ob[i] = fmaxf(fmaxf(m0, m1), 0.f);
    }
}

// ---------------- FC1 split-K partial: 64x64 tile, 4x4/thread, FFMA2 --------
__global__ void __launch_bounds__(256)
fc1_partial_kernel(const float* __restrict__ A,
                   const float* __restrict__ W,
                   float* __restrict__ partial) {
    __shared__ __align__(16) float sA[16][64];
    __shared__ __align__(16) float sW[16][64];

    const int tx = threadIdx.x, ty = threadIdx.y;     // 16x16
    const int t  = ty * 16 + tx;
    const int by = blockIdx.y, bx = blockIdx.x, kz = blockIdx.z;

    const int kchunk = (FC1IN + KSPLIT - 1) / KSPLIT;  // 908
    const int kbeg = kz * kchunk;
    const int kend = (kbeg + kchunk < FC1IN) ? (kbeg + kchunk) : FC1IN;

    u64 acc[4][2];
    #pragma unroll
    for (int i = 0; i < 4; ++i) { acc[i][0] = 0ULL; acc[i][1] = 0ULL; }

    const int mrow0 = by * 64;
    const int nrow0 = bx * 64;
    const int kp = t % 8;             // which k-pair (0..7) this thread loads

    for (int k0 = kbeg; k0 < kend; k0 += 16) {
        int gk = k0 + 2 * kp;
        bool kok = gk < kend;         // pairs never straddle (kend even)
        #pragma unroll
        for (int h = 0; h < 2; ++h) {
            int m = t / 8 + 32 * h;
            float2 va = kok ? *(const float2*)&A[(size_t)(mrow0 + m) * FC1IN + gk]
                            : make_float2(0.f, 0.f);
            sA[2 * kp][m]     = va.x;
            sA[2 * kp + 1][m] = va.y;
            int n = nrow0 + t / 8 + 32 * h;
            float2 vw = (kok && n < FC1OUT)
                        ? *(const float2*)&W[(size_t)n * FC1IN + gk]
                        : make_float2(0.f, 0.f);
            sW[2 * kp][t / 8 + 32 * h]     = vw.x;
            sW[2 * kp + 1][t / 8 + 32 * h] = vw.y;
        }
        __syncthreads();
        #pragma unroll
        for (int kk = 0; kk < 16; ++kk) {
            float4 a4 = *(const float4*)&sA[kk][ty * 4];
            u64 w01 = *(const u64*)&sW[kk][tx * 4];
            u64 w23 = *(const u64*)&sW[kk][tx * 4 + 2];
            u64 a0 = dup2(a4.x), a1 = dup2(a4.y), a2 = dup2(a4.z), a3 = dup2(a4.w);
            acc[0][0] = ffma2(a0, w01, acc[0][0]); acc[0][1] = ffma2(a0, w23, acc[0][1]);
            acc[1][0] = ffma2(a1, w01, acc[1][0]); acc[1][1] = ffma2(a1, w23, acc[1][1]);
            acc[2][0] = ffma2(a2, w01, acc[2][0]); acc[2][1] = ffma2(a2, w23, acc[2][1]);
            acc[3][0] = ffma2(a3, w01, acc[3][0]); acc[3][1] = ffma2(a3, w23, acc[3][1]);
        }
        __syncthreads();
    }

    float* pbase = partial + (size_t)kz * B_SZ * FC1OUT;
    const int n0 = nrow0 + tx * 4;
    #pragma unroll
    for (int i = 0; i < 4; ++i) {
        int m = mrow0 + ty * 4 + i;
        float2 vA = unpack2(acc[i][0]);
        float2 vB = unpack2(acc[i][1]);
        float* orow = pbase + (size_t)m * FC1OUT;
        if (n0     < FC1OUT) orow[n0]     = vA.x;
        if (n0 + 1 < FC1OUT) orow[n0 + 1] = vA.y;
        if (n0 + 2 < FC1OUT) orow[n0 + 2] = vB.x;
        if (n0 + 3 < FC1OUT) orow[n0 + 3] = vB.y;
    }
}

// ---------------- FC1 reduce: sum split-K partials + bias + ReLU ------------
__global__ void fc1_reduce_kernel(const float* __restrict__ partial,
                                  const float* __restrict__ bias,
                                  float* __restrict__ out) {
    int idx = blockIdx.x * blockDim.x + threadIdx.x;
    if (idx >= B_SZ * FC1OUT) return;
    int n = idx % FC1OUT;
    float v = bias[n];
    #pragma unroll
    for (int z = 0; z < KSPLIT; ++z)
        v += partial[(size_t)z * B_SZ * FC1OUT + idx];
    out[idx] = fmaxf(v, 0.f);
}

// ---------------- FC2 + sigmoid ----------------
__global__ void fc2_kernel(const float* __restrict__ A,
                           const float* __restrict__ W,
                           const float* __restrict__ bias,
                           float* __restrict__ out) {
    int idx = blockIdx.x * blockDim.x + threadIdx.x;  // b*2 + n
    if (idx >= B_SZ * FC2OUT) return;
    int b = idx >> 1, n = idx & 1;
    const float* a  = A + (size_t)b * FC1OUT;
    const float* wr = W + (size_t)n * FC1OUT;
    float acc = bias[n];
    #pragma unroll 8
    for (int k = 0; k < FC1OUT; ++k)
        acc = fmaf(a[k], wr[k], acc);
    out[idx] = 1.f / (1.f + expf(-acc));
}

// ---------------- launch ----------------
extern "C" void kernel_launch(void* const* d_in, const int* in_sizes, int n_in,
                              void* d_out, int out_size) {
    const float* x     = (const float*)d_in[0];
    const float* log_s = (const float*)d_in[1];
    const float* log_a = (const float*)d_in[2];
    const float* log_d = (const float*)d_in[3];
    const float* log_r = (const float*)d_in[4];
    const float* c1w   = (const float*)d_in[5];
    const float* c1b   = (const float*)d_in[6];
    const float* bn1g  = (const float*)d_in[7];
    const float* bn1b  = (const float*)d_in[8];
    const float* bn1m  = (const float*)d_in[9];
    const float* bn1v  = (const float*)d_in[10];
    const float* c2w   = (const float*)d_in[11];
    const float* c2b   = (const float*)d_in[12];
    const float* bn2g  = (const float*)d_in[13];
    const float* bn2b  = (const float*)d_in[14];
    const float* bn2m  = (const float*)d_in[15];
    const float* bn2v  = (const float*)d_in[16];
    const float* fc1w  = (const float*)d_in[17];
    const float* fc1b  = (const float*)d_in[18];
    const float* fc2w  = (const float*)d_in[19];
    const float* fc2b  = (const float*)d_in[20];
    float* out = (float*)d_out;

    float* pcen;  cudaGetSymbolAddress((void**)&pcen,  g_pcen);
    float* pool1; cudaGetSymbolAddress((void**)&pool1, g_pool1);
    float* pool2; cudaGetSymbolAddress((void**)&pool2, g_pool2);
    float* fc1p;  cudaGetSymbolAddress((void**)&fc1p,  g_fc1p);
    float* fc1o;  cudaGetSymbolAddress((void**)&fc1o,  g_fc1);

    // conv2-mma dynamic smem: (13050 + 56 + 64 + 26880) floats = 160200 B
    const int conv2_smem = (13050 + 56 + 64 + NSTEPS * 256) * 4;
    cudaFuncSetAttribute(conv2_mma_kernel,
                         cudaFuncAttributeMaxDynamicSharedMemorySize, conv2_smem);

    pcen_kernel<<<(B_SZ * HW + 255) / 256, 256>>>(x, log_s, log_a, log_d, log_r, pcen);

    conv1_kernel<<<dim3(B_SZ, 2), 224>>>(pcen, c1w, c1b, bn1g, bn1b, bn1m, bn1v, pool1);

    conv2_mma_kernel<<<B_SZ, 256, conv2_smem>>>(pool1, c2w, c2b, bn2g, bn2b, bn2m, bn2v, pool2);

    fc1_partial_kernel<<<dim3((FC1OUT + 63) / 64, B_SZ / 64, KSPLIT), dim3(16, 16)>>>(
        pool2, fc1w, fc1p);

    fc1_reduce_kernel<<<(B_SZ * FC1OUT + 255) / 256, 256>>>(fc1p, fc1b, fc1o);

    fc2_kernel<<<(B_SZ * FC2OUT + 255) / 256, 256>>>(fc1o, fc2w, fc2b, out);
}

// round 5
// speedup vs baseline: 5.1295x; 2.2981x over previous
#include <cuda_runtime.h>
#include <cuda_bf16.h>
#include <math.h>
#include <stdint.h>

#define B_SZ   2048
#define HW     64
#define C1     15
#define C2     30
#define P1     29          // pooled1 spatial (58/2)
#define P2     11          // pooled2 spatial (23/2 floor)
#define FC1IN  (C2*P2*P2)  // 3630
#define FC1OUT 200
#define FC2OUT 2
#define KSPLIT 4

typedef unsigned long long u64;

// ---------------- f32x2 packed helpers (Blackwell FFMA2) ----------------
__device__ __forceinline__ u64 ffma2(u64 a, u64 b, u64 c) {
    u64 d;
    asm("fma.rn.f32x2 %0, %1, %2, %3;" : "=l"(d) : "l"(a), "l"(b), "l"(c));
    return d;
}
__device__ __forceinline__ u64 pack2(float lo, float hi) {
    u64 d;
    asm("mov.b64 %0, {%1, %2};" : "=l"(d) : "f"(lo), "f"(hi));
    return d;
}
__device__ __forceinline__ u64 dup2(float v) { return pack2(v, v); }
__device__ __forceinline__ float2 unpack2(u64 v) {
    float2 r;
    asm("mov.b64 {%0, %1}, %2;" : "=f"(r.x), "=f"(r.y) : "l"(v));
    return r;
}
__device__ __forceinline__ float fex2(float x) {
    float y; asm("ex2.approx.f32 %0, %1;" : "=f"(y) : "f"(x)); return y;
}
__device__ __forceinline__ float flg2(float x) {
    float y; asm("lg2.approx.f32 %0, %1;" : "=f"(y) : "f"(x)); return y;
}
__device__ __forceinline__ float cvt_tf32(float x) {
    uint32_t u;
    asm("cvt.rna.tf32.f32 %0, %1;" : "=r"(u) : "f"(x));
    return __uint_as_float(u);
}
__device__ __forceinline__ uint32_t pack_bf16x2(float lo, float hi) {
    uint32_t d;
    asm("cvt.rn.bf16x2.f32 %0, %1, %2;" : "=r"(d) : "f"(hi), "f"(lo));
    return d;
}
// m16n8k8 tf32 MMA, fp32 accumulate
__device__ __forceinline__ void mma_tf32(float& c0, float& c1, float& c2, float& c3,
                                         uint32_t a0, uint32_t a1, uint32_t a2, uint32_t a3,
                                         uint32_t b0, uint32_t b1) {
    asm volatile(
        "mma.sync.aligned.m16n8k8.row.col.f32.tf32.tf32.f32 "
        "{%0,%1,%2,%3}, {%4,%5,%6,%7}, {%8,%9}, {%0,%1,%2,%3};"
        : "+f"(c0), "+f"(c1), "+f"(c2), "+f"(c3)
        : "r"(a0), "r"(a1), "r"(a2), "r"(a3), "r"(b0), "r"(b1));
}
// m16n8k16 bf16 MMA, fp32 accumulate
__device__ __forceinline__ void mma_bf16(float* c,
                                         uint32_t a0, uint32_t a1, uint32_t a2, uint32_t a3,
                                         uint32_t b0, uint32_t b1) {
    asm volatile(
        "mma.sync.aligned.m16n8k16.row.col.f32.bf16.bf16.f32 "
        "{%0,%1,%2,%3}, {%4,%5,%6,%7}, {%8,%9}, {%0,%1,%2,%3};"
        : "+f"(c[0]), "+f"(c[1]), "+f"(c[2]), "+f"(c[3])
        : "r"(a0), "r"(a1), "r"(a2), "r"(a3), "r"(b0), "r"(b1));
}

// ---------------- scratch (static device allocations) ----------------
__device__ float g_pcen [B_SZ * HW * HW];            // [B,64,64]
__device__ float g_pool1[B_SZ * C1 * P1 * P1];       // [B,15,29,29]
__device__ float g_pool2[B_SZ * C2 * P2 * P2];       // [B,30,11,11]
__device__ float g_fc1p [KSPLIT * B_SZ * FC1OUT];    // split-K partials
__device__ float g_fc1  [B_SZ * FC1OUT];             // [B,200]

// ---------------- PCEN: EMA over W per (b,h) row ----------------
__global__ void pcen_kernel(const float* __restrict__ x,
                            const float* __restrict__ log_s,
                            const float* __restrict__ log_alpha,
                            const float* __restrict__ log_delta,
                            const float* __restrict__ log_r,
                            float* __restrict__ out) {
    int idx = blockIdx.x * blockDim.x + threadIdx.x;   // b*64 + h
    if (idx >= B_SZ * HW) return;
    const float s     = expf(log_s[0]);
    const float alpha = expf(log_alpha[0]);
    const float delta = expf(log_delta[0]);
    const float r     = expf(log_r[0]);
    const float dr    = fex2(r * flg2(delta));
    const float* row  = x   + (size_t)idx * HW;
    float*       orow = out + (size_t)idx * HW;
    float m = 0.f;
    #pragma unroll 8
    for (int w = 0; w < HW; ++w) {
        float v = __ldg(row + w);
        m = (1.f - s) * m + s * v;                      // m0 = s*x0 (m starts 0)
        float t = fmaf(v, fex2(-alpha * flg2(m + 1e-6f)), delta);
        orow[w] = fex2(r * flg2(t)) - dr;
    }
}

// ---------------- conv1: transposed tf32 implicit GEMM ----------------------
// C[16 oc][3712 padded pos] per image. One CTA / image, 8 warps.
// M=16 (1 mtile), N tiles of 8 positions (58 rows x 64 padded cols), K=49->56.
// A (weights) fully register-hoisted; B gathered from resident 64x64 input;
// 2x2 maxpool completes in-thread (c0/c1 = horizontal pair, ntile-pair = rows).
__global__ void __launch_bounds__(256)
conv1_mma_kernel(const float* __restrict__ pcen,
                 const float* __restrict__ w,
                 const float* __restrict__ cb,
                 const float* __restrict__ g,
                 const float* __restrict__ beta,
                 const float* __restrict__ mean,
                 const float* __restrict__ var,
                 float* __restrict__ out) {
    __shared__ float sIn[HW * HW + 128];     // + slack (zeroed)
    __shared__ float sW[7 * 16 * 8];         // [krow j][oc][kcol] (kcol 7 = pad)
    __shared__ float sScale[16], sBias[16];

    const int b    = blockIdx.x;
    const int tid  = threadIdx.x;
    const int warp = tid >> 5;
    const int lane = tid & 31;
    const int gq   = lane >> 2;   // 0..7
    const int tg   = lane & 3;    // 0..3

    const float* in = pcen + (size_t)b * HW * HW;
    for (int i = tid; i < HW * HW + 128; i += 256)
        sIn[i] = (i < HW * HW) ? cvt_tf32(in[i]) : 0.f;
    for (int i = tid; i < 7 * 16 * 8; i += 256) {
        int j = i >> 7, rem = i & 127, oc = rem >> 3, k = rem & 7;
        float v = (oc < C1 && k < 7) ? w[oc * 49 + j * 7 + k] : 0.f;
        sW[i] = cvt_tf32(v);
    }
    if (tid < 16) {
        int oc = tid;
        if (oc < C1) {
            float inv = g[oc] * rsqrtf(var[oc] + 1e-5f);
            sScale[oc] = inv;
            sBias[oc]  = cb[oc] * inv + beta[oc] - mean[oc] * inv;
        } else { sScale[oc] = 0.f; sBias[oc] = 0.f; }
    }
    __syncthreads();

    // hoist A fragments: 7 ksteps x 4 regs
    uint32_t A[7][4];
    #pragma unroll
    for (int j = 0; j < 7; ++j) {
        const float* wj = sW + j * 128;
        A[j][0] = __float_as_uint(wj[gq * 8 + tg]);
        A[j][1] = __float_as_uint(wj[(gq + 8) * 8 + tg]);
        A[j][2] = __float_as_uint(wj[gq * 8 + tg + 4]);
        A[j][3] = __float_as_uint(wj[(gq + 8) * 8 + tg + 4]);
    }

    const float sA = sScale[gq],     bA = sBias[gq];
    const float sB = sScale[gq + 8], bB = sBias[gq + 8];
    float* ob = out + (size_t)b * C1 * (P1 * P1);
    const int px = (lane & 31, (tid & 0)) + 0;  // placeholder no-op

    // 232 ntile-pairs (29 row-pairs x 8 col-groups); warp handles 29
    for (int i = 0; i < 29; ++i) {
        int q  = warp + 8 * i;
        int y  = q >> 3, cg = q & 7;
        int pT = (2 * y) * HW + cg * 8 + gq;   // top-row position element idx

        float t0 = 0.f, t1 = 0.f, t2 = 0.f, t3 = 0.f;
        float u0 = 0.f, u1 = 0.f, u2 = 0.f, u3 = 0.f;
        #pragma unroll
        for (int j = 0; j < 7; ++j) {
            int base = pT + j * HW;
            uint32_t bT0 = __float_as_uint(sIn[base + tg]);
            uint32_t bT1 = __float_as_uint(sIn[base + tg + 4]);
            uint32_t bB0 = __float_as_uint(sIn[base + HW + tg]);
            uint32_t bB1 = __float_as_uint(sIn[base + HW + tg + 4]);
            mma_tf32(t0, t1, t2, t3, A[j][0], A[j][1], A[j][2], A[j][3], bT0, bT1);
            mma_tf32(u0, u1, u2, u3, A[j][0], A[j][1], A[j][2], A[j][3], bB0, bB1);
        }

        int pxo = cg * 4 + tg;
        if (pxo < P1) {
            // oc = gq : c0,c1 (pos pair) top + bottom
            float v = fmaxf(fmaxf(t0 * sA + bA, t1 * sA + bA),
                            fmaxf(u0 * sA + bA, u1 * sA + bA));
            ob[gq * (P1 * P1) + y * P1 + pxo] = fmaxf(v, 0.f);
            if (gq < 7) {   // oc = gq+8 (oc 15 = pad)
                float v2 = fmaxf(fmaxf(t2 * sB + bB, t3 * sB + bB),
                                 fmaxf(u2 * sB + bB, u3 * sB + bB));
                ob[(gq + 8) * (P1 * P1) + y * P1 + pxo] = fmaxf(v2, 0.f);
            }
        }
    }
}

// ---------------- conv2: transposed bf16 implicit GEMM ----------------------
// C[32 oc][528 padded pos] per image (22 rows x 24 padded cols). 352 threads
// (11 warps), each warp owns 3 ntile-pairs. K = 15 ic * 64 padded taps,
// k16 -> 60 ksteps. Input in dual-copy bf16 smem (parity-aligned u32 loads);
// shared middle row: 3 LDS feed 4 mma per pair-step. Pool in-thread.
__global__ void __launch_bounds__(352, 1)
conv2_mma_kernel(const float* __restrict__ pool1,
                 const float* __restrict__ w,
                 const float* __restrict__ cb,
                 const float* __restrict__ g,
                 const float* __restrict__ beta,
                 const float* __restrict__ mean,
                 const float* __restrict__ var,
                 float* __restrict__ out) {
    extern __shared__ char sm[];
    unsigned short* s0 = (unsigned short*)sm;             // copy0: 13920 bf16
    unsigned short* s1 = (unsigned short*)(sm + 27840);   // copy1 = shifted
    uint32_t* sW2  = (uint32_t*)(sm + 55680);             // [60][32][8] bf16x2
    float* sScale  = (float*)(sm + 55680 + 61440);
    float* sBias   = sScale + 32;

    const int b    = blockIdx.x;
    const int tid  = threadIdx.x;
    const int warp = tid / 32;
    const int lane = tid & 31;
    const int gq   = lane >> 2;
    const int tg   = lane & 3;

    // input fill: [ic][29 rows][32 cols] bf16, cols 29..31 zero; dual copy
    const float* in = pool1 + (size_t)b * C1 * (P1 * P1);
    for (int E = tid; E < 13920; E += 352) {
        int ic = E / 928, rem = E % 928, row = rem >> 5, col = rem & 31;
        float v = (col < P1) ? in[ic * (P1 * P1) + row * P1 + col] : 0.f;
        __nv_bfloat16 h = __float2bfloat16(v);
        unsigned short u = *(unsigned short*)&h;
        s0[E] = u;
        if (E > 0) s1[E - 1] = u;
    }
    if (tid == 0) s1[13919] = 0;

    // weight fill: sW2[ks][oc][pair], ks = ic*4 + j; taps padded per-row to 8,
    // per-ic to 64; pair p = taps (16j+2p, 16j+2p+1)
    for (int i = tid; i < 15360; i += 352) {
        int pr = i & 7, oc = (i >> 3) & 31, ks = i >> 8;
        int ic = ks >> 2, j = ks & 3;
        int k0 = 16 * j + 2 * pr;
        int kr = k0 >> 3, kc = k0 & 7;       // k0 even -> pair same row
        float w0 = (kr < 7 && kc < 7 && oc < C2) ? w[oc * 735 + ic * 49 + kr * 7 + kc] : 0.f;
        float w1 = (kr < 7 && kc + 1 < 7 && oc < C2) ? w[oc * 735 + ic * 49 + kr * 7 + kc + 1] : 0.f;
        sW2[i] = pack_bf16x2(w0, w1);
    }
    if (tid < 32) {
        int oc = tid;
        if (oc < C2) {
            float inv = g[oc] * rsqrtf(var[oc] + 1e-5f);
            sScale[oc] = inv;
            sBias[oc]  = cb[oc] * inv + beta[oc] - mean[oc] * inv;
        } else { sScale[oc] = 0.f; sBias[oc] = 0.f; }
    }
    __syncthreads();

    // parity-aligned base pointer: even-gq lanes read copy0 at 2E,
    // odd-gq lanes read copy1 at 2(E-1)
    const char* bp = (gq & 1) ? (sm + 27840 - 2) : sm;

    // warp's 3 ntile-pairs: q = warp*3 + i -> (y = q/3, cg = q%3)
    int P[3], Y[3], CG[3];
    #pragma unroll
    for (int i = 0; i < 3; ++i) {
        int q = warp * 3 + i;
        Y[i] = q / 3; CG[i] = q % 3;
        P[i] = (2 * Y[i]) * 32 + CG[i] * 8 + gq + 2 * tg;   // E offset (incl k-col)
    }

    float accT[3][2][4], accB[3][2][4];
    #pragma unroll
    for (int i = 0; i < 3; ++i)
        #pragma unroll
        for (int m = 0; m < 2; ++m)
            #pragma unroll
            for (int qd = 0; qd < 4; ++qd) { accT[i][m][qd] = 0.f; accB[i][m][qd] = 0.f; }

    for (int ic = 0; ic < C1; ++ic) {
        #pragma unroll
        for (int j = 0; j < 4; ++j) {
            const uint32_t* wp = sW2 + (ic * 4 + j) * 256;
            uint32_t a00 = wp[gq * 8 + tg],        a01 = wp[(gq + 8) * 8 + tg];
            uint32_t a02 = wp[gq * 8 + tg + 4],    a03 = wp[(gq + 8) * 8 + tg + 4];
            uint32_t a10 = wp[(gq + 16) * 8 + tg], a11 = wp[(gq + 24) * 8 + tg];
            uint32_t a12 = wp[(gq + 16) * 8 + tg + 4], a13 = wp[(gq + 24) * 8 + tg + 4];
            int ebase = ic * 928 + j * 64;
            #pragma unroll
            for (int i = 0; i < 3; ++i) {
                int E = ebase + P[i];
                uint32_t v0 = *(const uint32_t*)(bp + 2 * E);
                uint32_t v1 = *(const uint32_t*)(bp + 2 * E + 64);
                uint32_t v2 = *(const uint32_t*)(bp + 2 * E + 128);
                mma_bf16(accT[i][0], a00, a01, a02, a03, v0, v1);
                mma_bf16(accT[i][1], a10, a11, a12, a13, v0, v1);
                mma_bf16(accB[i][0], a00, a01, a02, a03, v1, v2);
                mma_bf16(accB[i][1], a10, a11, a12, a13, v1, v2);
            }
        }
    }

    // epilogue: scale/bias -> 2x2 pool (in-thread) -> ReLU -> gmem
    float* ob = out + (size_t)b * (C2 * P2 * P2);
    #pragma unroll
    for (int i = 0; i < 3; ++i) {
        int pxo = CG[i] * 4 + tg;
        if (pxo >= P2) continue;     // cg=2, tg=3 -> pad columns
        #pragma unroll
        for (int m = 0; m < 2; ++m) {
            #pragma unroll
            for (int h = 0; h < 2; ++h) {
                int oc = gq + 8 * h + 16 * m;
                if (oc >= C2) continue;
                float s = sScale[oc], bb = sBias[oc];
                float v = fmaxf(fmaxf(accT[i][m][2 * h] * s + bb,
                                      accT[i][m][2 * h + 1] * s + bb),
                                fmaxf(accB[i][m][2 * h] * s + bb,
                                      accB[i][m][2 * h + 1] * s + bb));
                ob[oc * (P2 * P2) + Y[i] * P2 + pxo] = fmaxf(v, 0.f);
            }
        }
    }
}

// ---------------- FC1 split-K partial: 64x64 tile, 4x4/thread, FFMA2 --------
__global__ void __launch_bounds__(256)
fc1_partial_kernel(const float* __restrict__ A,
                   const float* __restrict__ W,
                   float* __restrict__ partial) {
    __shared__ __align__(16) float sA[16][64];
    __shared__ __align__(16) float sW[16][64];

    const int tx = threadIdx.x, ty = threadIdx.y;     // 16x16
    const int t  = ty * 16 + tx;
    const int by = blockIdx.y, bx = blockIdx.x, kz = blockIdx.z;

    const int kchunk = (FC1IN + KSPLIT - 1) / KSPLIT;  // 908
    const int kbeg = kz * kchunk;
    const int kend = (kbeg + kchunk < FC1IN) ? (kbeg + kchunk) : FC1IN;

    u64 acc[4][2];
    #pragma unroll
    for (int i = 0; i < 4; ++i) { acc[i][0] = 0ULL; acc[i][1] = 0ULL; }

    const int mrow0 = by * 64;
    const int nrow0 = bx * 64;
    const int kp = t % 8;

    for (int k0 = kbeg; k0 < kend; k0 += 16) {
        int gk = k0 + 2 * kp;
        bool kok = gk < kend;
        #pragma unroll
        for (int h = 0; h < 2; ++h) {
            int m = t / 8 + 32 * h;
            float2 va = kok ? *(const float2*)&A[(size_t)(mrow0 + m) * FC1IN + gk]
                            : make_float2(0.f, 0.f);
            sA[2 * kp][m]     = va.x;
            sA[2 * kp + 1][m] = va.y;
            int n = nrow0 + t / 8 + 32 * h;
            float2 vw = (kok && n < FC1OUT)
                        ? *(const float2*)&W[(size_t)n * FC1IN + gk]
                        : make_float2(0.f, 0.f);
            sW[2 * kp][t / 8 + 32 * h]     = vw.x;
            sW[2 * kp + 1][t / 8 + 32 * h] = vw.y;
        }
        __syncthreads();
        #pragma unroll
        for (int kk = 0; kk < 16; ++kk) {
            float4 a4 = *(const float4*)&sA[kk][ty * 4];
            u64 w01 = *(const u64*)&sW[kk][tx * 4];
            u64 w23 = *(const u64*)&sW[kk][tx * 4 + 2];
            u64 a0 = dup2(a4.x), a1 = dup2(a4.y), a2 = dup2(a4.z), a3 = dup2(a4.w);
            acc[0][0] = ffma2(a0, w01, acc[0][0]); acc[0][1] = ffma2(a0, w23, acc[0][1]);
            acc[1][0] = ffma2(a1, w01, acc[1][0]); acc[1][1] = ffma2(a1, w23, acc[1][1]);
            acc[2][0] = ffma2(a2, w01, acc[2][0]); acc[2][1] = ffma2(a2, w23, acc[2][1]);
            acc[3][0] = ffma2(a3, w01, acc[3][0]); acc[3][1] = ffma2(a3, w23, acc[3][1]);
        }
        __syncthreads();
    }

    float* pbase = partial + (size_t)kz * B_SZ * FC1OUT;
    const int n0 = nrow0 + tx * 4;
    #pragma unroll
    for (int i = 0; i < 4; ++i) {
        int m = mrow0 + ty * 4 + i;
        float2 vA = unpack2(acc[i][0]);
        float2 vB = unpack2(acc[i][1]);
        float* orow = pbase + (size_t)m * FC1OUT;
        if (n0     < FC1OUT) orow[n0]     = vA.x;
        if (n0 + 1 < FC1OUT) orow[n0 + 1] = vA.y;
        if (n0 + 2 < FC1OUT) orow[n0 + 2] = vB.x;
        if (n0 + 3 < FC1OUT) orow[n0 + 3] = vB.y;
    }
}

// ---------------- FC1 reduce: sum split-K partials + bias + ReLU ------------
__global__ void fc1_reduce_kernel(const float* __restrict__ partial,
                                  const float* __restrict__ bias,
                                  float* __restrict__ out) {
    int idx = blockIdx.x * blockDim.x + threadIdx.x;
    if (idx >= B_SZ * FC1OUT) return;
    int n = idx % FC1OUT;
    float v = bias[n];
    #pragma unroll
    for (int z = 0; z < KSPLIT; ++z)
        v += partial[(size_t)z * B_SZ * FC1OUT + idx];
    out[idx] = fmaxf(v, 0.f);
}

// ---------------- FC2 + sigmoid ----------------
__global__ void fc2_kernel(const float* __restrict__ A,
                           const float* __restrict__ W,
                           const float* __restrict__ bias,
                           float* __restrict__ out) {
    int idx = blockIdx.x * blockDim.x + threadIdx.x;  // b*2 + n
    if (idx >= B_SZ * FC2OUT) return;
    int b = idx >> 1, n = idx & 1;
    const float* a  = A + (size_t)b * FC1OUT;
    const float* wr = W + (size_t)n * FC1OUT;
    float acc = bias[n];
    #pragma unroll 8
    for (int k = 0; k < FC1OUT; ++k)
        acc = fmaf(a[k], wr[k], acc);
    out[idx] = 1.f / (1.f + expf(-acc));
}

// ---------------- launch ----------------
extern "C" void kernel_launch(void* const* d_in, const int* in_sizes, int n_in,
                              void* d_out, int out_size) {
    const float* x     = (const float*)d_in[0];
    const float* log_s = (const float*)d_in[1];
    const float* log_a = (const float*)d_in[2];
    const float* log_d = (const float*)d_in[3];
    const float* log_r = (const float*)d_in[4];
    const float* c1w   = (const float*)d_in[5];
    const float* c1b   = (const float*)d_in[6];
    const float* bn1g  = (const float*)d_in[7];
    const float* bn1b  = (const float*)d_in[8];
    const float* bn1m  = (const float*)d_in[9];
    const float* bn1v  = (const float*)d_in[10];
    const float* c2w   = (const float*)d_in[11];
    const float* c2b   = (const float*)d_in[12];
    const float* bn2g  = (const float*)d_in[13];
    const float* bn2b  = (const float*)d_in[14];
    const float* bn2m  = (const float*)d_in[15];
    const float* bn2v  = (const float*)d_in[16];
    const float* fc1w  = (const float*)d_in[17];
    const float* fc1b  = (const float*)d_in[18];
    const float* fc2w  = (const float*)d_in[19];
    const float* fc2b  = (const float*)d_in[20];
    float* out = (float*)d_out;

    float* pcen;  cudaGetSymbolAddress((void**)&pcen,  g_pcen);
    float* pool1; cudaGetSymbolAddress((void**)&pool1, g_pool1);
    float* pool2; cudaGetSymbolAddress((void**)&pool2, g_pool2);
    float* fc1p;  cudaGetSymbolAddress((void**)&fc1p,  g_fc1p);
    float* fc1o;  cudaGetSymbolAddress((void**)&fc1o,  g_fc1);

    // conv2 smem: 2*27840 (bf16 dual copy) + 61440 (weights) + 256 = 117376 B
    const int conv2_smem = 55680 + 61440 + 256;
    cudaFuncSetAttribute(conv2_mma_kernel,
                         cudaFuncAttributeMaxDynamicSharedMemorySize, conv2_smem);

    pcen_kernel<<<(B_SZ * HW + 255) / 256, 256>>>(x, log_s, log_a, log_d, log_r, pcen);

    conv1_mma_kernel<<<B_SZ, 256>>>(pcen, c1w, c1b, bn1g, bn1b, bn1m, bn1v, pool1);

    conv2_mma_kernel<<<B_SZ, 352, conv2_smem>>>(pool1, c2w, c2b, bn2g, bn2b, bn2m, bn2v, pool2);

    fc1_partial_kernel<<<dim3((FC1OUT + 63) / 64, B_SZ / 64, KSPLIT), dim3(16, 16)>>>(
        pool2, fc1w, fc1p);

    fc1_reduce_kernel<<<(B_SZ * FC1OUT + 255) / 256, 256>>>(fc1p, fc1b, fc1o);

    fc2_kernel<<<(B_SZ * FC2OUT + 255) / 256, 256>>>(fc1o, fc2w, fc2b, out);
}